// round 6
// baseline (speedup 1.0000x reference)
#include <cuda_runtime.h>
#include <cuda_bf16.h>
#include <float.h>
#include <stdint.h>

#define NN   50000
#define EE   250000
#define ET   300000
#define NG   64

// ---------------------------------------------------------------------------
// Device scratch
// ---------------------------------------------------------------------------
__device__ __align__(16) float g_P[(size_t)NN * 1024];   // h2 / h3
__device__ __align__(16) float g_Q[(size_t)NN * 1024];   // o1 / o2 / o3
__device__ __align__(16) float g_z[(size_t)NN * 88];     // layer-1 aggregated x

__device__ float g_als[NN * 8];
__device__ float g_ald[NN * 8];
__device__ float g_ws[11 * 8];
__device__ float g_wd[11 * 8];

__device__ int   g_srcS[ET];
__device__ int   g_deg[NN];
__device__ int   g_off[NN + 1];
__device__ int   g_cur[NN];

__device__ int g_ei64;
__device__ int g_b64;

__device__ __forceinline__ int clampN(int v) {
    return (v < 0) ? 0 : ((v >= NN) ? NN - 1 : v);
}

// ---------------------------------------------------------------------------
// Parallel dtype detection (int32 vs int64 index inputs)
// ---------------------------------------------------------------------------
__global__ void k_detect(const int* __restrict__ ei, const int* __restrict__ batch) {
    int t = threadIdx.x;   // 1024 threads
    int ok1 = (ei[2 * t + 1] == 0);                 // odd words of first 1024 elements
    int idx = NN - 1024 + t;                        // tail of batch (int32 view)
    int ok2 = ((idx & 1) == 0) || (batch[idx] == 0);
    int a1 = __syncthreads_and(ok1);
    int a2 = __syncthreads_and(ok2);
    if (t == 0) { g_ei64 = a1; g_b64 = a2; }
}

__device__ __forceinline__ int ld_ei(const int* __restrict__ ei, int i) {
    return g_ei64 ? ei[2 * i] : ei[i];
}
__device__ __forceinline__ int ld_b(const int* __restrict__ b, int i) {
    return g_b64 ? b[2 * i] : b[i];
}

// ---------------------------------------------------------------------------
// CSR build
// ---------------------------------------------------------------------------
__global__ void k_zero_deg() {
    int i = blockIdx.x * blockDim.x + threadIdx.x;
    if (i < NN) g_deg[i] = 0;
}

__global__ void k_count(const int* __restrict__ ei) {
    int e = blockIdx.x * blockDim.x + threadIdx.x;
    if (e >= ET) return;
    int dst = (e < EE) ? clampN(ld_ei(ei, EE + e)) : (e - EE);
    atomicAdd(&g_deg[dst], 1);
}

// Two-level warp-shuffle exclusive scan; also initializes g_cur.
__global__ void k_scan() {   // 1 block, 1024 threads
    int tid = threadIdx.x;
    const int SZ = (NN + 1023) / 1024;   // 49
    int lo = tid * SZ; if (lo > NN) lo = NN;
    int hi = lo + SZ;  if (hi > NN) hi = NN;
    int s = 0;
    for (int i = lo; i < hi; i++) s += g_deg[i];

    int lane = tid & 31, wid = tid >> 5;
    int v = s;
#pragma unroll
    for (int o = 1; o < 32; o <<= 1) {
        int u = __shfl_up_sync(0xFFFFFFFFu, v, o);
        if (lane >= o) v += u;
    }
    __shared__ int wsum[32];
    if (lane == 31) wsum[wid] = v;
    __syncthreads();
    if (wid == 0) {
        int w = wsum[lane];
#pragma unroll
        for (int o = 1; o < 32; o <<= 1) {
            int u = __shfl_up_sync(0xFFFFFFFFu, w, o);
            if (lane >= o) w += u;
        }
        wsum[lane] = w;
    }
    __syncthreads();
    int excl = v - s + ((wid > 0) ? wsum[wid - 1] : 0);
    int run = excl;
    for (int i = lo; i < hi; i++) {
        g_off[i] = run;
        g_cur[i] = run;
        run += g_deg[i];
    }
    if (tid == 1023) g_off[NN] = excl;   // strip empty -> excl == total
}

__global__ void k_scatter(const int* __restrict__ ei) {
    int e = blockIdx.x * blockDim.x + threadIdx.x;
    if (e >= ET) return;
    int src, dst;
    if (e < EE) { src = clampN(ld_ei(ei, e)); dst = clampN(ld_ei(ei, EE + e)); }
    else        { src = e - EE;               dst = e - EE; }
    int pos = atomicAdd(&g_cur[dst], 1);
    if (pos >= 0 && pos < ET) g_srcS[pos] = src;
}

// ---------------------------------------------------------------------------
// Layer-1 algebraic path: ws[k][h] = sum_c W1[k][h*128+c]*a1s[h][c]
// ---------------------------------------------------------------------------
__global__ void k_wsd(const float* __restrict__ W1, const float* __restrict__ a1s,
                      const float* __restrict__ a1d) {
    int t = threadIdx.x;
    if (t >= 88) return;
    int k = t / 8, h = t % 8;
    float ss = 0.f, sd = 0.f;
    const float* wrow = W1 + k * 1024 + h * 128;
    const float* asr  = a1s + h * 128;
    const float* adr  = a1d + h * 128;
    for (int c = 0; c < 128; c++) {
        float w = wrow[c];
        ss += w * asr[c];
        sd += w * adr[c];
    }
    g_ws[k * 8 + h] = ss;
    g_wd[k * 8 + h] = sd;
}

__global__ void k_alx(const float* __restrict__ x) {
    __shared__ float ws[88], wd[88];
    int t = threadIdx.x;
    if (t < 88) { ws[t] = g_ws[t]; wd[t] = g_wd[t]; }
    __syncthreads();
    int n = blockIdx.x * blockDim.x + t;
    if (n >= NN) return;
    float xv[11];
#pragma unroll
    for (int k = 0; k < 11; k++) xv[k] = x[n * 11 + k];
#pragma unroll
    for (int h = 0; h < 8; h++) {
        float ps = 0.f, pd = 0.f;
#pragma unroll
        for (int k = 0; k < 11; k++) {
            ps += xv[k] * ws[k * 8 + h];
            pd += xv[k] * wd[k * 8 + h];
        }
        g_als[n * 8 + h] = ps;
        g_ald[n * 8 + h] = pd;
    }
}

// Layer-1 aggregation with fused streaming softmax (thread per node).
__global__ void k_aggx(const float* __restrict__ x) {
    int n = blockIdx.x * blockDim.x + threadIdx.x;
    if (n >= NN) return;
    float ad[8], m[8], s[8];
#pragma unroll
    for (int h = 0; h < 8; h++) {
        ad[h] = g_ald[n * 8 + h];
        m[h] = -FLT_MAX;
        s[h] = 0.f;
    }
    int s0 = g_off[n], s1 = g_off[n + 1];
    // pass 1: streaming max + sum
    for (int j = s0; j < s1; j++) {
        int src = g_srcS[j];
#pragma unroll
        for (int h = 0; h < 8; h++) {
            float e = g_als[src * 8 + h] + ad[h];
            e = fmaxf(e, 0.2f * e);
            if (e > m[h]) { s[h] *= __expf(m[h] - e); m[h] = e; }
            s[h] += __expf(e - m[h]);
        }
    }
    float dv[8];
#pragma unroll
    for (int h = 0; h < 8; h++) dv[h] = 1.f / (s[h] + 1e-16f);
    // pass 2: weighted accumulate
    float z[88];
#pragma unroll
    for (int i = 0; i < 88; i++) z[i] = 0.f;
    for (int j = s0; j < s1; j++) {
        int src = g_srcS[j];
        float xs_[11];
#pragma unroll
        for (int k = 0; k < 11; k++) xs_[k] = x[src * 11 + k];
#pragma unroll
        for (int h = 0; h < 8; h++) {
            float e = g_als[src * 8 + h] + ad[h];
            e = fmaxf(e, 0.2f * e);
            float a = __expf(e - m[h]) * dv[h];
#pragma unroll
            for (int k = 0; k < 11; k++) z[h * 11 + k] += a * xs_[k];
        }
    }
#pragma unroll
    for (int i = 0; i < 88; i++) g_z[(size_t)n * 88 + i] = z[i];
}

// o1[n][h*128+c] = lrelu( z[n][h] . W1[:, h*128+c] + b1 )
__global__ __launch_bounds__(256) void k_proj(const float* __restrict__ W1,
                                              const float* __restrict__ b1,
                                              float* __restrict__ o1) {
    __shared__ float Wh[11][128];
    __shared__ float zt[64][11];
    int n0 = blockIdx.x * 64;
    int h = blockIdx.y;
    int t = threadIdx.x;
    for (int i = t; i < 11 * 128; i += 256) {
        int k = i >> 7, c = i & 127;
        Wh[k][c] = W1[k * 1024 + h * 128 + c];
    }
    for (int i = t; i < 64 * 11; i += 256) {
        int r = i / 11, k = i - r * 11;
        int n = n0 + r;
        zt[r][k] = (n < NN) ? g_z[(size_t)n * 88 + h * 11 + k] : 0.f;
    }
    __syncthreads();
    int c = t & 127;
    int r0 = (t >> 7) * 32;
    float bias = b1[h * 128 + c];
#pragma unroll 4
    for (int i = 0; i < 32; i++) {
        int r = r0 + i;
        int n = n0 + r;
        if (n >= NN) break;
        float acc = bias;
#pragma unroll
        for (int k = 0; k < 11; k++) acc += zt[r][k] * Wh[k][c];
        o1[(size_t)n * 1024 + h * 128 + c] = (acc > 0.f) ? acc : 0.01f * acc;
    }
}

// ---------------------------------------------------------------------------
// 3xTF32 tensor-core GEMM, hi/lo split at tile load.
// C(Nrows x M) = A(Nrows x K) @ B(K x M). BM=128, BN=64, BK=16.
// ---------------------------------------------------------------------------
__device__ __forceinline__ void mma_tf32(float* c, const uint32_t* a, const uint32_t* b) {
    asm volatile(
        "mma.sync.aligned.m16n8k8.row.col.f32.tf32.tf32.f32 "
        "{%0,%1,%2,%3}, {%4,%5,%6,%7}, {%8,%9}, {%0,%1,%2,%3};"
        : "+f"(c[0]), "+f"(c[1]), "+f"(c[2]), "+f"(c[3])
        : "r"(a[0]), "r"(a[1]), "r"(a[2]), "r"(a[3]), "r"(b[0]), "r"(b[1]));
}

__device__ __forceinline__ void split_tf32(float v, uint32_t& hi, uint32_t& lo) {
    uint32_t h;
    asm("cvt.rna.tf32.f32 %0, %1;" : "=r"(h) : "f"(v));
    float rem = v - __uint_as_float(h);
    asm("cvt.rna.tf32.f32 %0, %1;" : "=r"(lo) : "f"(rem));
    hi = h;
}

#define APITCH 136   // 136 % 32 == 8 -> conflict-free fragment loads
#define BPITCH 72    // 72 % 32 == 8

__global__ __launch_bounds__(256) void k_sgemm_tc(const float* __restrict__ A,
                                                  const float* __restrict__ B,
                                                  float* __restrict__ C,
                                                  int Nrows, int K, int M) {
    __shared__ uint32_t Ah[16][APITCH], Al[16][APITCH];
    __shared__ uint32_t Bh[16][BPITCH], Bl[16][BPITCH];
    int tid = threadIdx.x;
    int lane = tid & 31, warp = tid >> 5;
    int g = lane >> 2, tg = lane & 3;
    int rowBase = blockIdx.x * 128;
    int colBase = blockIdx.y * 64;
    int warpM = (warp & 1) * 64;
    int warpN = (warp >> 1) * 16;

    float acc[4][2][4];
#pragma unroll
    for (int mt = 0; mt < 4; mt++)
#pragma unroll
        for (int nt = 0; nt < 2; nt++)
#pragma unroll
            for (int i = 0; i < 4; i++) acc[mt][nt][i] = 0.f;

    int arow = tid >> 1;                 // 0..127
    int ak4  = (tid & 1) * 8;            // 0 or 8
    bool avalid = (rowBase + arow) < Nrows;
    const float* Abase = A + (size_t)(rowBase + arow) * K + ak4;

    int brow = tid >> 4;                 // 0..15
    int bcol = (tid & 15) * 4;           // 0..60
    const float* Bbase = B + (size_t)brow * M + colBase + bcol;

    for (int kt = 0; kt < K; kt += 16) {
        // ---- load + split A (8 elems/thread) ----
        float4 a0 = avalid ? *(const float4*)(Abase + kt)     : make_float4(0, 0, 0, 0);
        float4 a1 = avalid ? *(const float4*)(Abase + kt + 4) : make_float4(0, 0, 0, 0);
        // ---- load + split B (4 elems/thread) ----
        float4 bv = *(const float4*)(Bbase + (size_t)kt * M);
        __syncthreads();
        {
            float av[8] = {a0.x, a0.y, a0.z, a0.w, a1.x, a1.y, a1.z, a1.w};
#pragma unroll
            for (int j = 0; j < 8; j++) {
                uint32_t h, l;
                split_tf32(av[j], h, l);
                Ah[ak4 + j][arow] = h;
                Al[ak4 + j][arow] = l;
            }
            float bw[4] = {bv.x, bv.y, bv.z, bv.w};
#pragma unroll
            for (int j = 0; j < 4; j++) {
                uint32_t h, l;
                split_tf32(bw[j], h, l);
                Bh[brow][bcol + j] = h;
                Bl[brow][bcol + j] = l;
            }
        }
        __syncthreads();

#pragma unroll
        for (int kk = 0; kk < 16; kk += 8) {
            uint32_t a_h[4][4], a_l[4][4];
#pragma unroll
            for (int mt = 0; mt < 4; mt++) {
                int r0 = warpM + mt * 16 + g;
                a_h[mt][0] = Ah[kk + tg][r0];
                a_h[mt][1] = Ah[kk + tg][r0 + 8];
                a_h[mt][2] = Ah[kk + tg + 4][r0];
                a_h[mt][3] = Ah[kk + tg + 4][r0 + 8];
                a_l[mt][0] = Al[kk + tg][r0];
                a_l[mt][1] = Al[kk + tg][r0 + 8];
                a_l[mt][2] = Al[kk + tg + 4][r0];
                a_l[mt][3] = Al[kk + tg + 4][r0 + 8];
            }
#pragma unroll
            for (int nt = 0; nt < 2; nt++) {
                int c0 = warpN + nt * 8 + g;
                uint32_t b_h[2], b_l[2];
                b_h[0] = Bh[kk + tg][c0];
                b_h[1] = Bh[kk + tg + 4][c0];
                b_l[0] = Bl[kk + tg][c0];
                b_l[1] = Bl[kk + tg + 4][c0];
#pragma unroll
                for (int mt = 0; mt < 4; mt++) {
                    mma_tf32(acc[mt][nt], a_h[mt], b_h);
                    mma_tf32(acc[mt][nt], a_h[mt], b_l);
                    mma_tf32(acc[mt][nt], a_l[mt], b_h);
                }
            }
        }
    }

#pragma unroll
    for (int mt = 0; mt < 4; mt++) {
#pragma unroll
        for (int nt = 0; nt < 2; nt++) {
            int r = rowBase + warpM + mt * 16 + g;
            int cc = colBase + warpN + nt * 8 + tg * 2;
            if (r < Nrows)
                *(float2*)&C[(size_t)r * M + cc] = make_float2(acc[mt][nt][0], acc[mt][nt][1]);
            if (r + 8 < Nrows)
                *(float2*)&C[(size_t)(r + 8) * M + cc] = make_float2(acc[mt][nt][2], acc[mt][nt][3]);
        }
    }
}

// ---------------------------------------------------------------------------
// al_s / al_d per (node, head) from dense h
// ---------------------------------------------------------------------------
template <int OUT, int C, int H>
__global__ void k_al(const float* __restrict__ h, const float* __restrict__ as,
                     const float* __restrict__ ad, float* __restrict__ als,
                     float* __restrict__ ald) {
    constexpr int R = C / 32;
    int n = blockIdx.x, t = threadIdx.x;   // blockDim == H*32
    const float* hp = h + (size_t)n * OUT + t * R;
    float ps = 0.f, pd = 0.f;
#pragma unroll
    for (int j = 0; j < R; j++) {
        float v = hp[j];
        ps += v * as[t * R + j];
        pd += v * ad[t * R + j];
    }
#pragma unroll
    for (int o = 16; o > 0; o >>= 1) {
        ps += __shfl_down_sync(0xFFFFFFFFu, ps, o);
        pd += __shfl_down_sync(0xFFFFFFFFu, pd, o);
    }
    if ((t & 31) == 0) {
        int w = t >> 5;
        als[n * H + w] = ps;
        ald[n * H + w] = pd;
    }
}

// ---------------------------------------------------------------------------
// Aggregation with fused streaming softmax stats.
// out[n] = lrelu_{0.01}( sum_e alpha * h[src] + bias )
// ---------------------------------------------------------------------------
template <int OUT, int H, int C>
__global__ void k_agg(const float* __restrict__ h, const float* __restrict__ als,
                      const float* __restrict__ ald, const float* __restrict__ bias,
                      float* __restrict__ out) {
    constexpr int T = (OUT < 256) ? OUT : 256;
    constexpr int R = OUT / T;
    __shared__ int   ssrc[32];
    __shared__ float sE[32 * H];
    __shared__ float sM[H], sS[H], sAld[H], sDv[H];
    int n = blockIdx.x, t = threadIdx.x;
    int myhead = (t * R) / C;

    if (t < H) { sM[t] = -FLT_MAX; sS[t] = 0.f; sAld[t] = ald[n * H + t]; }
    __syncthreads();

    int s0 = g_off[n], s1 = g_off[n + 1];

    // phase A: streaming max + sum per head
    for (int e0 = s0; e0 < s1; e0 += 32) {
        int cs = min(32, s1 - e0);
        if (t < cs) ssrc[t] = g_srcS[e0 + t];
        __syncthreads();
        if (t < cs * H) {
            int i = t / H, hh = t - i * H;
            float e = als[ssrc[i] * H + hh] + sAld[hh];
            sE[t] = fmaxf(e, 0.2f * e);
        }
        __syncthreads();
        if (t < H) {
            float m = sM[t], s = sS[t];
            for (int i = 0; i < cs; i++) {
                float e = sE[i * H + t];
                if (e > m) { s *= __expf(m - e); m = e; }
                s += __expf(e - m);
            }
            sM[t] = m; sS[t] = s;
        }
        __syncthreads();
    }
    if (t < H) sDv[t] = 1.f / (sS[t] + 1e-16f);
    __syncthreads();

    float acc[R];
#pragma unroll
    for (int j = 0; j < R; j++) acc[j] = 0.f;

    // phase B: alpha + accumulate
    for (int e0 = s0; e0 < s1; e0 += 32) {
        int cs = min(32, s1 - e0);
        if (t < cs) ssrc[t] = g_srcS[e0 + t];
        __syncthreads();
        if (t < cs * H) {
            int i = t / H, hh = t - i * H;
            float e = als[ssrc[i] * H + hh] + sAld[hh];
            e = fmaxf(e, 0.2f * e);
            sE[t] = __expf(e - sM[hh]) * sDv[hh];
        }
        __syncthreads();
        for (int i = 0; i < cs; i++) {
            float a = sE[i * H + myhead];
            const float* hp = h + (size_t)ssrc[i] * OUT + t * R;
            if constexpr (R == 2) {
                float2 v = *(const float2*)hp;
                acc[0] += a * v.x; acc[1] += a * v.y;
            } else {
                acc[0] += a * hp[0];
            }
        }
        __syncthreads();
    }
#pragma unroll
    for (int j = 0; j < R; j++) {
        float v = acc[j] + bias[t * R + j];
        out[(size_t)n * OUT + t * R + j] = (v > 0.f) ? v : 0.01f * v;
    }
}

// ---------------------------------------------------------------------------
// Pooling + head: batch sorted -> per-graph contiguous ranges.
// ---------------------------------------------------------------------------
__device__ __forceinline__ int lower_bound_b(const int* __restrict__ b, int val) {
    int lo = 0, hi = NN;
    while (lo < hi) {
        int mid = (lo + hi) >> 1;
        if (ld_b(b, mid) < val) lo = mid + 1; else hi = mid;
    }
    return lo;
}

__global__ void k_poolseg(const int* __restrict__ batch, const float* __restrict__ o3,
                          const float* __restrict__ Wout, const float* __restrict__ bout,
                          float* __restrict__ out) {
    int gph = blockIdx.x, t = threadIdx.x;   // 128 threads
    int lo = lower_bound_b(batch, gph);
    int hi = lower_bound_b(batch, gph + 1);
    float s = 0.f;
    for (int n = lo; n < hi; n++) s += o3[(size_t)n * 128 + t];
    float cnt = fmaxf((float)(hi - lo), 1.f);
    float v = (s / cnt) * Wout[t];
#pragma unroll
    for (int o = 16; o > 0; o >>= 1) v += __shfl_down_sync(0xFFFFFFFFu, v, o);
    __shared__ float red[4];
    if ((t & 31) == 0) red[t >> 5] = v;
    __syncthreads();
    if (t == 0) out[gph] = red[0] + red[1] + red[2] + red[3] + bout[0];
}

// ---------------------------------------------------------------------------
// Launch
// ---------------------------------------------------------------------------
extern "C" void kernel_launch(void* const* d_in, const int* in_sizes, int n_in,
                              void* d_out, int out_size) {
    int ix = 0, iei = 1, ib = 2, iW1 = 3, ia1s = 4, ia1d = 5, ib1 = 6,
        iW2 = 7, ia2s = 8, ia2d = 9, ib2 = 10, iW3 = 11, ia3s = 12,
        ia3d = 13, ib3 = 14, iWout = 15, ibout = 16;
    {
        int jx = -1, jei = -1, jb = -1, jW1 = -1, jW2 = -1, jW3 = -1, jbout = -1;
        int j1024[3], n1024 = 0;
        int j512[3],  n512 = 0;
        int j128[4],  n128 = 0;
        bool clean = true;
        for (int i = 0; i < n_in; i++) {
            int s = in_sizes[i];
            if      (s == 550000) { if (jx >= 0) clean = false; jx = i; }
            else if (s == 500000) { if (jei >= 0) clean = false; jei = i; }
            else if (s == 50000)  { if (jb >= 0) clean = false; jb = i; }
            else if (s == 11264)  { if (jW1 >= 0) clean = false; jW1 = i; }
            else if (s == 524288) { if (jW2 >= 0) clean = false; jW2 = i; }
            else if (s == 65536)  { if (jW3 >= 0) clean = false; jW3 = i; }
            else if (s == 1024)   { if (n1024 < 3) j1024[n1024] = i; n1024++; }
            else if (s == 512)    { if (n512  < 3) j512[n512]   = i; n512++; }
            else if (s == 128)    { if (n128  < 4) j128[n128]   = i; n128++; }
            else if (s == 1)      { if (jbout >= 0) clean = false; jbout = i; }
            else clean = false;
        }
        if (clean && jx >= 0 && jei >= 0 && jb >= 0 && jW1 >= 0 && jW2 >= 0 &&
            jW3 >= 0 && jbout >= 0 && n1024 == 3 && n512 == 3 && n128 == 4) {
            ix = jx; iei = jei; ib = jb; iW1 = jW1; iW2 = jW2; iW3 = jW3;
            ia1s = j1024[0]; ia1d = j1024[1]; ib1 = j1024[2];
            ia2s = j512[0];  ia2d = j512[1];  ib2 = j512[2];
            ia3s = j128[0];  ia3d = j128[1];  ib3 = j128[2]; iWout = j128[3];
            ibout = jbout;
        }
    }

    const float* x    = (const float*)d_in[ix];
    const int*   ei   = (const int*)d_in[iei];
    const int*   batch= (const int*)d_in[ib];
    const float* W1   = (const float*)d_in[iW1];
    const float* a1s  = (const float*)d_in[ia1s];
    const float* a1d  = (const float*)d_in[ia1d];
    const float* b1   = (const float*)d_in[ib1];
    const float* W2   = (const float*)d_in[iW2];
    const float* a2s  = (const float*)d_in[ia2s];
    const float* a2d  = (const float*)d_in[ia2d];
    const float* b2   = (const float*)d_in[ib2];
    const float* W3   = (const float*)d_in[iW3];
    const float* a3s  = (const float*)d_in[ia3s];
    const float* a3d  = (const float*)d_in[ia3d];
    const float* b3   = (const float*)d_in[ib3];
    const float* Wout = (const float*)d_in[iWout];
    const float* bout = (const float*)d_in[ibout];
    float* out = (float*)d_out;

    float* P = nullptr;   cudaGetSymbolAddress((void**)&P, g_P);
    float* Q = nullptr;   cudaGetSymbolAddress((void**)&Q, g_Q);
    float* als = nullptr; cudaGetSymbolAddress((void**)&als, g_als);
    float* ald = nullptr; cudaGetSymbolAddress((void**)&ald, g_ald);

    // CSR build + layer-1 attention precompute
    k_detect<<<1, 1024>>>(ei, batch);
    k_zero_deg<<<(NN + 255) / 256, 256>>>();
    k_count<<<(ET + 255) / 256, 256>>>(ei);
    k_scan<<<1, 1024>>>();
    k_scatter<<<(ET + 255) / 256, 256>>>(ei);

    // ---- Layer 1 (algebraic): o1 = Q ----
    k_wsd<<<1, 128>>>(W1, a1s, a1d);
    k_alx<<<(NN + 255) / 256, 256>>>(x);
    k_aggx<<<(NN + 127) / 128, 128>>>(x);
    {
        dim3 grid((NN + 63) / 64, 8);
        k_proj<<<grid, 256>>>(W1, b1, Q);
    }

    // ---- Layer 2: h2 = Q @ W2 (3xTF32 TC), agg -> Q ----
    {
        dim3 grid((NN + 127) / 128, 512 / 64);
        k_sgemm_tc<<<grid, 256>>>(Q, W2, P, NN, 1024, 512);
        k_al<512, 64, 8><<<NN, 256>>>(P, a2s, a2d, als, ald);
        k_agg<512, 8, 64><<<NN, 256>>>(P, als, ald, b2, Q);
    }

    // ---- Layer 3: h3 = Q @ W3 (3xTF32 TC), agg -> Q ----
    {
        dim3 grid((NN + 127) / 128, 128 / 64);
        k_sgemm_tc<<<grid, 256>>>(Q, W3, P, NN, 512, 128);
        k_al<128, 32, 4><<<NN, 128>>>(P, a3s, a3d, als, ald);
        k_agg<128, 4, 32><<<NN, 128>>>(P, als, ald, b3, Q);
    }

    // ---- Pool + head ----
    k_poolseg<<<NG, 128>>>(batch, Q, Wout, bout, out);
}

// round 7
// speedup vs baseline: 1.2292x; 1.2292x over previous
#include <cuda_runtime.h>
#include <cuda_bf16.h>
#include <float.h>
#include <stdint.h>

#define NN   50000
#define EE   250000
#define ET   300000
#define NG   64

// ---------------------------------------------------------------------------
// Device scratch
// ---------------------------------------------------------------------------
__device__ __align__(16) float g_P[(size_t)NN * 1024];   // h2 / h3
__device__ __align__(16) float g_Q[(size_t)NN * 1024];   // o1 / o2 / o3
__device__ __align__(16) float g_z[(size_t)NN * 88];     // layer-1 aggregated x

__device__ float g_als[NN * 8];
__device__ float g_ald[NN * 8];
__device__ float g_emax[NN * 8];
__device__ float g_dinv[NN * 8];
__device__ float g_ws[11 * 8];
__device__ float g_wd[11 * 8];

__device__ int   g_srcS[ET];
__device__ int   g_deg[NN];
__device__ int   g_off[NN + 1];
__device__ int   g_cur[NN];

__device__ int g_ei64;
__device__ int g_b64;

__device__ __forceinline__ int clampN(int v) {
    return (v < 0) ? 0 : ((v >= NN) ? NN - 1 : v);
}

// ---------------------------------------------------------------------------
// Parallel dtype detection (int32 vs int64 index inputs)
// ---------------------------------------------------------------------------
__global__ void k_detect(const int* __restrict__ ei, const int* __restrict__ batch) {
    int t = threadIdx.x;   // 1024 threads
    int ok1 = (ei[2 * t + 1] == 0);                 // odd words of first 1024 elems
    int idx = NN - 1024 + t;                        // tail of batch (int32 view)
    int ok2 = ((idx & 1) == 0) || (batch[idx] == 0);
    int a1 = __syncthreads_and(ok1);
    int a2 = __syncthreads_and(ok2);
    if (t == 0) { g_ei64 = a1; g_b64 = a2; }
}

__device__ __forceinline__ int ld_ei(const int* __restrict__ ei, int i) {
    return g_ei64 ? ei[2 * i] : ei[i];
}
__device__ __forceinline__ int ld_b(const int* __restrict__ b, int i) {
    return g_b64 ? b[2 * i] : b[i];
}

// ---------------------------------------------------------------------------
// CSR build
// ---------------------------------------------------------------------------
__global__ void k_zero_deg() {
    int i = blockIdx.x * blockDim.x + threadIdx.x;
    if (i < NN) g_deg[i] = 0;
}

__global__ void k_count(const int* __restrict__ ei) {
    int e = blockIdx.x * blockDim.x + threadIdx.x;
    if (e >= ET) return;
    int dst = (e < EE) ? clampN(ld_ei(ei, EE + e)) : (e - EE);
    atomicAdd(&g_deg[dst], 1);
}

// Strip-based exclusive scan (R5-measured); also initializes g_cur.
__global__ void k_scan_simple() {   // 1 block, 1024 threads
    __shared__ int strip[1024];
    int tid = threadIdx.x;
    const int SZ = (NN + 1023) / 1024;
    int lo = tid * SZ; if (lo > NN) lo = NN;
    int hi = lo + SZ;  if (hi > NN) hi = NN;
    int s = 0;
    for (int i = lo; i < hi; i++) s += g_deg[i];
    strip[tid] = s;
    __syncthreads();
    if (tid == 0) {
        int run = 0;
        for (int i = 0; i < 1024; i++) { int t = strip[i]; strip[i] = run; run += t; }
        g_off[NN] = run;
    }
    __syncthreads();
    int run = strip[tid];
    for (int i = lo; i < hi; i++) {
        g_off[i] = run;
        g_cur[i] = run;
        run += g_deg[i];
    }
}

__global__ void k_scatter(const int* __restrict__ ei) {
    int e = blockIdx.x * blockDim.x + threadIdx.x;
    if (e >= ET) return;
    int src, dst;
    if (e < EE) { src = clampN(ld_ei(ei, e)); dst = clampN(ld_ei(ei, EE + e)); }
    else        { src = e - EE;               dst = e - EE; }
    int pos = atomicAdd(&g_cur[dst], 1);
    if (pos >= 0 && pos < ET) g_srcS[pos] = src;
}

// ---------------------------------------------------------------------------
// Layer-1 algebraic path
// ---------------------------------------------------------------------------
__global__ void k_wsd(const float* __restrict__ W1, const float* __restrict__ a1s,
                      const float* __restrict__ a1d) {
    int t = threadIdx.x;
    if (t >= 88) return;
    int k = t / 8, h = t % 8;
    float ss = 0.f, sd = 0.f;
    const float* wrow = W1 + k * 1024 + h * 128;
    const float* asr  = a1s + h * 128;
    const float* adr  = a1d + h * 128;
    for (int c = 0; c < 128; c++) {
        float w = wrow[c];
        ss += w * asr[c];
        sd += w * adr[c];
    }
    g_ws[k * 8 + h] = ss;
    g_wd[k * 8 + h] = sd;
}

__global__ void k_alx(const float* __restrict__ x) {
    __shared__ float ws[88], wd[88];
    int t = threadIdx.x;
    if (t < 88) { ws[t] = g_ws[t]; wd[t] = g_wd[t]; }
    __syncthreads();
    int n = blockIdx.x * blockDim.x + t;
    if (n >= NN) return;
    float xv[11];
#pragma unroll
    for (int k = 0; k < 11; k++) xv[k] = x[n * 11 + k];
#pragma unroll
    for (int h = 0; h < 8; h++) {
        float ps = 0.f, pd = 0.f;
#pragma unroll
        for (int k = 0; k < 11; k++) {
            ps += xv[k] * ws[k * 8 + h];
            pd += xv[k] * wd[k * 8 + h];
        }
        g_als[n * 8 + h] = ps;
        g_ald[n * 8 + h] = pd;
    }
}

// softmax stats per (node, head)
template <int H>
__global__ void k_stats(const float* __restrict__ als, const float* __restrict__ ald,
                        float* __restrict__ emax, float* __restrict__ dinv) {
    int idx = blockIdx.x * blockDim.x + threadIdx.x;
    if (idx >= NN * H) return;
    int n = idx / H, hh = idx - n * H;
    float ad = ald[idx];
    int s0 = g_off[n], s1 = g_off[n + 1];
    float m = -FLT_MAX;
    for (int j = s0; j < s1; j++) {
        float e = als[g_srcS[j] * H + hh] + ad;
        e = fmaxf(e, 0.2f * e);
        m = fmaxf(m, e);
    }
    float ssum = 0.f;
    for (int j = s0; j < s1; j++) {
        float e = als[g_srcS[j] * H + hh] + ad;
        e = fmaxf(e, 0.2f * e);
        ssum += __expf(e - m);
    }
    emax[idx] = m;
    dinv[idx] = 1.f / (ssum + 1e-16f);
}

// z[n][h][k] = sum_e alpha_eh * x[src_e][k]   (thread per node)
__global__ void k_aggx(const float* __restrict__ x) {
    int n = blockIdx.x * blockDim.x + threadIdx.x;
    if (n >= NN) return;
    float z[88];
#pragma unroll
    for (int i = 0; i < 88; i++) z[i] = 0.f;
    float ad[8], em[8], dv[8];
#pragma unroll
    for (int h = 0; h < 8; h++) {
        ad[h] = g_ald[n * 8 + h];
        em[h] = g_emax[n * 8 + h];
        dv[h] = g_dinv[n * 8 + h];
    }
    int s0 = g_off[n], s1 = g_off[n + 1];
    for (int j = s0; j < s1; j++) {
        int s = g_srcS[j];
        float xs_[11];
#pragma unroll
        for (int k = 0; k < 11; k++) xs_[k] = x[s * 11 + k];
#pragma unroll
        for (int h = 0; h < 8; h++) {
            float e = g_als[s * 8 + h] + ad[h];
            e = fmaxf(e, 0.2f * e);
            float a = __expf(e - em[h]) * dv[h];
#pragma unroll
            for (int k = 0; k < 11; k++) z[h * 11 + k] += a * xs_[k];
        }
    }
#pragma unroll
    for (int i = 0; i < 88; i++) g_z[(size_t)n * 88 + i] = z[i];
}

// o1[n][h*128+c] = lrelu( z[n][h] . W1[:, h*128+c] + b1 )
__global__ __launch_bounds__(256) void k_proj(const float* __restrict__ W1,
                                              const float* __restrict__ b1,
                                              float* __restrict__ o1) {
    __shared__ float Wh[11][128];
    __shared__ float zt[64][11];
    int n0 = blockIdx.x * 64;
    int h = blockIdx.y;
    int t = threadIdx.x;
    for (int i = t; i < 11 * 128; i += 256) {
        int k = i >> 7, c = i & 127;
        Wh[k][c] = W1[k * 1024 + h * 128 + c];
    }
    for (int i = t; i < 64 * 11; i += 256) {
        int r = i / 11, k = i - r * 11;
        int n = n0 + r;
        zt[r][k] = (n < NN) ? g_z[(size_t)n * 88 + h * 11 + k] : 0.f;
    }
    __syncthreads();
    int c = t & 127;
    int r0 = (t >> 7) * 32;
    float bias = b1[h * 128 + c];
#pragma unroll 4
    for (int i = 0; i < 32; i++) {
        int r = r0 + i;
        int n = n0 + r;
        if (n >= NN) break;
        float acc = bias;
#pragma unroll
        for (int k = 0; k < 11; k++) acc += zt[r][k] * Wh[k][c];
        o1[(size_t)n * 1024 + h * 128 + c] = (acc > 0.f) ? acc : 0.01f * acc;
    }
}

// ---------------------------------------------------------------------------
// TF32 tensor-core GEMM with 3xTF32 error compensation (R5-measured config).
// C(Nrows x M) = A(Nrows x K) @ B(K x M). BM=128, BN=128, BK=32.
// ---------------------------------------------------------------------------
__device__ __forceinline__ void mma_tf32(float* c, const uint32_t* a, const uint32_t* b) {
    asm volatile(
        "mma.sync.aligned.m16n8k8.row.col.f32.tf32.tf32.f32 "
        "{%0,%1,%2,%3}, {%4,%5,%6,%7}, {%8,%9}, {%0,%1,%2,%3};"
        : "+f"(c[0]), "+f"(c[1]), "+f"(c[2]), "+f"(c[3])
        : "r"(a[0]), "r"(a[1]), "r"(a[2]), "r"(a[3]), "r"(b[0]), "r"(b[1]));
}

__device__ __forceinline__ void split_tf32(float v, uint32_t& hi, uint32_t& lo) {
    uint32_t h;
    asm("cvt.rna.tf32.f32 %0, %1;" : "=r"(h) : "f"(v));
    float rem = v - __uint_as_float(h);
    asm("cvt.rna.tf32.f32 %0, %1;" : "=r"(lo) : "f"(rem));
    hi = h;
}

__global__ __launch_bounds__(256) void k_sgemm_tc(const float* __restrict__ A,
                                                  const float* __restrict__ B,
                                                  float* __restrict__ C,
                                                  int Nrows, int K, int M) {
    __shared__ float As[32][132];   // [k][m]
    __shared__ float Bs[32][132];   // [k][n]
    int tid = threadIdx.x;
    int lane = tid & 31, warp = tid >> 5;
    int g = lane >> 2, tg = lane & 3;
    int rowBase = blockIdx.x * 128;
    int colBase = blockIdx.y * 128;
    int warpM = (warp & 1) * 64;
    int warpN = (warp >> 1) * 32;

    float c[4][4][4];
#pragma unroll
    for (int mt = 0; mt < 4; mt++)
#pragma unroll
        for (int nt = 0; nt < 4; nt++)
#pragma unroll
            for (int i = 0; i < 4; i++) c[mt][nt][i] = 0.f;

    for (int kt = 0; kt < K; kt += 32) {
        // load A tile (transposed into As[k][m])
        {
            int row = tid >> 1;
            int gr = rowBase + row;
            bool v = gr < Nrows;
            const float* ap = A + (size_t)gr * K + kt;
#pragma unroll
            for (int i = 0; i < 4; i++) {
                int k4 = ((tid & 1) + 2 * i) * 4;
                float4 av = v ? *(const float4*)(ap + k4) : make_float4(0, 0, 0, 0);
                As[k4 + 0][row] = av.x;
                As[k4 + 1][row] = av.y;
                As[k4 + 2][row] = av.z;
                As[k4 + 3][row] = av.w;
            }
        }
        // load B tile
        {
            int row = tid >> 3;
            const float* bp = B + (size_t)(kt + row) * M + colBase;
#pragma unroll
            for (int i = 0; i < 4; i++) {
                int col = ((tid & 7) + 8 * i) * 4;
                float4 bv = *(const float4*)(bp + col);
                *(float4*)&Bs[row][col] = bv;
            }
        }
        __syncthreads();

#pragma unroll
        for (int kk = 0; kk < 32; kk += 8) {
            uint32_t ah[4][4], al[4][4], bh[4][2], bl[4][2];
#pragma unroll
            for (int mt = 0; mt < 4; mt++) {
                int r0 = warpM + mt * 16 + g;
                float a0 = As[kk + tg][r0];
                float a1 = As[kk + tg][r0 + 8];
                float a2 = As[kk + tg + 4][r0];
                float a3 = As[kk + tg + 4][r0 + 8];
                split_tf32(a0, ah[mt][0], al[mt][0]);
                split_tf32(a1, ah[mt][1], al[mt][1]);
                split_tf32(a2, ah[mt][2], al[mt][2]);
                split_tf32(a3, ah[mt][3], al[mt][3]);
            }
#pragma unroll
            for (int nt = 0; nt < 4; nt++) {
                int c0i = warpN + nt * 8 + g;
                float b0 = Bs[kk + tg][c0i];
                float b1 = Bs[kk + tg + 4][c0i];
                split_tf32(b0, bh[nt][0], bl[nt][0]);
                split_tf32(b1, bh[nt][1], bl[nt][1]);
            }
#pragma unroll
            for (int mt = 0; mt < 4; mt++)
#pragma unroll
                for (int nt = 0; nt < 4; nt++) {
                    mma_tf32(c[mt][nt], ah[mt], bh[nt]);
                    mma_tf32(c[mt][nt], ah[mt], bl[nt]);
                    mma_tf32(c[mt][nt], al[mt], bh[nt]);
                }
        }
        __syncthreads();
    }

#pragma unroll
    for (int mt = 0; mt < 4; mt++) {
#pragma unroll
        for (int nt = 0; nt < 4; nt++) {
            int r = rowBase + warpM + mt * 16 + g;
            int cc = colBase + warpN + nt * 8 + tg * 2;
            if (r < Nrows)
                *(float2*)&C[(size_t)r * M + cc] = make_float2(c[mt][nt][0], c[mt][nt][1]);
            if (r + 8 < Nrows)
                *(float2*)&C[(size_t)(r + 8) * M + cc] = make_float2(c[mt][nt][2], c[mt][nt][3]);
        }
    }
}

// ---------------------------------------------------------------------------
// al_s / al_d per (node, head) from dense h
// ---------------------------------------------------------------------------
template <int OUT, int C, int H>
__global__ void k_al(const float* __restrict__ h, const float* __restrict__ as,
                     const float* __restrict__ ad, float* __restrict__ als,
                     float* __restrict__ ald) {
    constexpr int R = C / 32;
    int n = blockIdx.x, t = threadIdx.x;   // blockDim == H*32
    const float* hp = h + (size_t)n * OUT + t * R;
    float ps = 0.f, pd = 0.f;
#pragma unroll
    for (int j = 0; j < R; j++) {
        float v = hp[j];
        ps += v * as[t * R + j];
        pd += v * ad[t * R + j];
    }
#pragma unroll
    for (int o = 16; o > 0; o >>= 1) {
        ps += __shfl_down_sync(0xFFFFFFFFu, ps, o);
        pd += __shfl_down_sync(0xFFFFFFFFu, pd, o);
    }
    if ((t & 31) == 0) {
        int w = t >> 5;
        als[n * H + w] = ps;
        ald[n * H + w] = pd;
    }
}

// ---------------------------------------------------------------------------
// Aggregation: out[n] = lrelu_{0.01}( sum_e alpha * h[src] + bias )
// ---------------------------------------------------------------------------
template <int OUT, int H, int C>
__global__ void k_agg(const float* __restrict__ h, const float* __restrict__ als,
                      const float* __restrict__ ald, const float* __restrict__ emax,
                      const float* __restrict__ dinv, const float* __restrict__ bias,
                      float* __restrict__ out) {
    constexpr int T = (OUT < 256) ? OUT : 256;
    constexpr int R = OUT / T;
    __shared__ int   ssrc[32];
    __shared__ float salpha[32 * H];
    int n = blockIdx.x, t = threadIdx.x;
    int myhead = (t * R) / C;

    float acc[R];
#pragma unroll
    for (int j = 0; j < R; j++) acc[j] = 0.f;

    int s0 = g_off[n], s1 = g_off[n + 1];
    for (int e0 = s0; e0 < s1; e0 += 32) {
        int cs = min(32, s1 - e0);
        if (t < cs) ssrc[t] = g_srcS[e0 + t];
        __syncthreads();
        if (t < cs * H) {
            int i = t / H, hh = t - i * H;
            float e = als[ssrc[i] * H + hh] + ald[n * H + hh];
            e = fmaxf(e, 0.2f * e);
            salpha[i * H + hh] = __expf(e - emax[n * H + hh]) * dinv[n * H + hh];
        }
        __syncthreads();
        for (int i = 0; i < cs; i++) {
            float a = salpha[i * H + myhead];
            const float* hp = h + (size_t)ssrc[i] * OUT + t * R;
            if constexpr (R == 2) {
                float2 v = *(const float2*)hp;
                acc[0] += a * v.x; acc[1] += a * v.y;
            } else {
                acc[0] += a * hp[0];
            }
        }
        __syncthreads();
    }
#pragma unroll
    for (int j = 0; j < R; j++) {
        float v = acc[j] + bias[t * R + j];
        out[(size_t)n * OUT + t * R + j] = (v > 0.f) ? v : 0.01f * v;
    }
}

// ---------------------------------------------------------------------------
// Pooling + head: batch sorted -> per-graph contiguous ranges.
// ---------------------------------------------------------------------------
__device__ __forceinline__ int lower_bound_b(const int* __restrict__ b, int val) {
    int lo = 0, hi = NN;
    while (lo < hi) {
        int mid = (lo + hi) >> 1;
        if (ld_b(b, mid) < val) lo = mid + 1; else hi = mid;
    }
    return lo;
}

__global__ void k_poolseg(const int* __restrict__ batch, const float* __restrict__ o3,
                          const float* __restrict__ Wout, const float* __restrict__ bout,
                          float* __restrict__ out) {
    int gph = blockIdx.x, t = threadIdx.x;   // 128 threads
    int lo = lower_bound_b(batch, gph);
    int hi = lower_bound_b(batch, gph + 1);
    float s = 0.f;
    for (int n = lo; n < hi; n++) s += o3[(size_t)n * 128 + t];
    float cnt = fmaxf((float)(hi - lo), 1.f);
    float v = (s / cnt) * Wout[t];
#pragma unroll
    for (int o = 16; o > 0; o >>= 1) v += __shfl_down_sync(0xFFFFFFFFu, v, o);
    __shared__ float red[4];
    if ((t & 31) == 0) red[t >> 5] = v;
    __syncthreads();
    if (t == 0) out[gph] = red[0] + red[1] + red[2] + red[3] + bout[0];
}

// ---------------------------------------------------------------------------
// Launch
// ---------------------------------------------------------------------------
extern "C" void kernel_launch(void* const* d_in, const int* in_sizes, int n_in,
                              void* d_out, int out_size) {
    int ix = 0, iei = 1, ib = 2, iW1 = 3, ia1s = 4, ia1d = 5, ib1 = 6,
        iW2 = 7, ia2s = 8, ia2d = 9, ib2 = 10, iW3 = 11, ia3s = 12,
        ia3d = 13, ib3 = 14, iWout = 15, ibout = 16;
    {
        int jx = -1, jei = -1, jb = -1, jW1 = -1, jW2 = -1, jW3 = -1, jbout = -1;
        int j1024[3], n1024 = 0;
        int j512[3],  n512 = 0;
        int j128[4],  n128 = 0;
        bool clean = true;
        for (int i = 0; i < n_in; i++) {
            int s = in_sizes[i];
            if      (s == 550000) { if (jx >= 0) clean = false; jx = i; }
            else if (s == 500000) { if (jei >= 0) clean = false; jei = i; }
            else if (s == 50000)  { if (jb >= 0) clean = false; jb = i; }
            else if (s == 11264)  { if (jW1 >= 0) clean = false; jW1 = i; }
            else if (s == 524288) { if (jW2 >= 0) clean = false; jW2 = i; }
            else if (s == 65536)  { if (jW3 >= 0) clean = false; jW3 = i; }
            else if (s == 1024)   { if (n1024 < 3) j1024[n1024] = i; n1024++; }
            else if (s == 512)    { if (n512  < 3) j512[n512]   = i; n512++; }
            else if (s == 128)    { if (n128  < 4) j128[n128]   = i; n128++; }
            else if (s == 1)      { if (jbout >= 0) clean = false; jbout = i; }
            else clean = false;
        }
        if (clean && jx >= 0 && jei >= 0 && jb >= 0 && jW1 >= 0 && jW2 >= 0 &&
            jW3 >= 0 && jbout >= 0 && n1024 == 3 && n512 == 3 && n128 == 4) {
            ix = jx; iei = jei; ib = jb; iW1 = jW1; iW2 = jW2; iW3 = jW3;
            ia1s = j1024[0]; ia1d = j1024[1]; ib1 = j1024[2];
            ia2s = j512[0];  ia2d = j512[1];  ib2 = j512[2];
            ia3s = j128[0];  ia3d = j128[1];  ib3 = j128[2]; iWout = j128[3];
            ibout = jbout;
        }
    }

    const float* x    = (const float*)d_in[ix];
    const int*   ei   = (const int*)d_in[iei];
    const int*   batch= (const int*)d_in[ib];
    const float* W1   = (const float*)d_in[iW1];
    const float* a1s  = (const float*)d_in[ia1s];
    const float* a1d  = (const float*)d_in[ia1d];
    const float* b1   = (const float*)d_in[ib1];
    const float* W2   = (const float*)d_in[iW2];
    const float* a2s  = (const float*)d_in[ia2s];
    const float* a2d  = (const float*)d_in[ia2d];
    const float* b2   = (const float*)d_in[ib2];
    const float* W3   = (const float*)d_in[iW3];
    const float* a3s  = (const float*)d_in[ia3s];
    const float* a3d  = (const float*)d_in[ia3d];
    const float* b3   = (const float*)d_in[ib3];
    const float* Wout = (const float*)d_in[iWout];
    const float* bout = (const float*)d_in[ibout];
    float* out = (float*)d_out;

    float* P = nullptr;   cudaGetSymbolAddress((void**)&P, g_P);
    float* Q = nullptr;   cudaGetSymbolAddress((void**)&Q, g_Q);
    float* als = nullptr; cudaGetSymbolAddress((void**)&als, g_als);
    float* ald = nullptr; cudaGetSymbolAddress((void**)&ald, g_ald);
    float* emax = nullptr; cudaGetSymbolAddress((void**)&emax, g_emax);
    float* dinv = nullptr; cudaGetSymbolAddress((void**)&dinv, g_dinv);

    // dtype detection + CSR build
    k_detect<<<1, 1024>>>(ei, batch);
    k_zero_deg<<<(NN + 255) / 256, 256>>>();
    k_count<<<(ET + 255) / 256, 256>>>(ei);
    k_scan_simple<<<1, 1024>>>();
    k_scatter<<<(ET + 255) / 256, 256>>>(ei);

    // ---- Layer 1 (algebraic): o1 = Q ----
    k_wsd<<<1, 128>>>(W1, a1s, a1d);
    k_alx<<<(NN + 255) / 256, 256>>>(x);
    k_stats<8><<<(NN * 8 + 255) / 256, 256>>>(als, ald, emax, dinv);
    k_aggx<<<(NN + 127) / 128, 128>>>(x);
    {
        dim3 grid((NN + 63) / 64, 8);
        k_proj<<<grid, 256>>>(W1, b1, Q);
    }

    // ---- Layer 2: h2 = Q @ W2 (3xTF32 TC), agg -> Q ----
    {
        dim3 grid((NN + 127) / 128, 4);
        k_sgemm_tc<<<grid, 256>>>(Q, W2, P, NN, 1024, 512);
        k_al<512, 64, 8><<<NN, 256>>>(P, a2s, a2d, als, ald);
        k_stats<8><<<(NN * 8 + 255) / 256, 256>>>(als, ald, emax, dinv);
        k_agg<512, 8, 64><<<NN, 256>>>(P, als, ald, emax, dinv, b2, Q);
    }

    // ---- Layer 3: h3 = Q @ W3 (3xTF32 TC), agg -> Q ----
    {
        dim3 grid((NN + 127) / 128, 1);
        k_sgemm_tc<<<grid, 256>>>(Q, W3, P, NN, 512, 128);
        k_al<128, 32, 4><<<NN, 128>>>(P, a3s, a3d, als, ald);
        k_stats<4><<<(NN * 4 + 255) / 256, 256>>>(als, ald, emax, dinv);
        k_agg<128, 4, 32><<<NN, 128>>>(P, als, ald, emax, dinv, b3, Q);
    }

    // ---- Pool + head ----
    k_poolseg<<<NG, 128>>>(batch, Q, Wout, bout, out);
}

// round 8
// speedup vs baseline: 1.3393x; 1.0896x over previous
#include <cuda_runtime.h>
#include <cuda_bf16.h>
#include <float.h>
#include <stdint.h>

#define NN   50000
#define EE   250000
#define ET   300000
#define NG   64

// ---------------------------------------------------------------------------
// Device scratch
// ---------------------------------------------------------------------------
__device__ __align__(16) float g_P[(size_t)NN * 1024];   // h2 / h3
__device__ __align__(16) float g_Q[(size_t)NN * 1024];   // o1 / o2 / o3
__device__ __align__(16) float g_z[(size_t)NN * 88];     // layer-1 aggregated x

__device__ float g_als[NN * 8];
__device__ float g_ald[NN * 8];
__device__ float g_emax[NN * 8];
__device__ float g_dinv[NN * 8];
__device__ float g_ws[11 * 8];
__device__ float g_wd[11 * 8];

__device__ int   g_srcS[ET];
__device__ int   g_deg[NN];
__device__ int   g_off[NN + 1];
__device__ int   g_cur[NN];
__device__ int   g_bsum[64];
__device__ int   g_boff[64];

__device__ int g_ei64;
__device__ int g_b64;

__device__ __forceinline__ int clampN(int v) {
    return (v < 0) ? 0 : ((v >= NN) ? NN - 1 : v);
}

// ---------------------------------------------------------------------------
// Parallel dtype detection (int32 vs int64 index inputs)
// ---------------------------------------------------------------------------
__global__ void k_detect(const int* __restrict__ ei, const int* __restrict__ batch) {
    int t = threadIdx.x;   // 1024 threads
    int ok1 = (ei[2 * t + 1] == 0);
    int idx = NN - 1024 + t;
    int ok2 = ((idx & 1) == 0) || (batch[idx] == 0);
    int a1 = __syncthreads_and(ok1);
    int a2 = __syncthreads_and(ok2);
    if (t == 0) { g_ei64 = a1; g_b64 = a2; }
}

__device__ __forceinline__ int ld_ei(const int* __restrict__ ei, int i) {
    return g_ei64 ? ei[2 * i] : ei[i];
}
__device__ __forceinline__ int ld_b(const int* __restrict__ b, int i) {
    return g_b64 ? b[2 * i] : b[i];
}

// ---------------------------------------------------------------------------
// CSR build
// ---------------------------------------------------------------------------
__global__ void k_zero_deg() {
    int i = blockIdx.x * blockDim.x + threadIdx.x;
    if (i < NN) g_deg[i] = 0;
}

__global__ void k_count(const int* __restrict__ ei) {
    int e = blockIdx.x * blockDim.x + threadIdx.x;
    if (e >= ET) return;
    int dst = (e < EE) ? clampN(ld_ei(ei, EE + e)) : (e - EE);
    atomicAdd(&g_deg[dst], 1);
}

// ---- 3-kernel parallel scan: 50 blocks x 1000 nodes ----
__global__ void k_scan1() {   // grid 50, block 1024: block partial sums
    int b = blockIdx.x, t = threadIdx.x;
    int i = b * 1000 + t;
    int v = (t < 1000 && i < NN) ? g_deg[i] : 0;
#pragma unroll
    for (int o = 16; o > 0; o >>= 1) v += __shfl_down_sync(0xFFFFFFFFu, v, o);
    __shared__ int w[32];
    int lane = t & 31, wid = t >> 5;
    if (lane == 0) w[wid] = v;
    __syncthreads();
    if (wid == 0) {
        int x = w[lane];
#pragma unroll
        for (int o = 16; o > 0; o >>= 1) x += __shfl_down_sync(0xFFFFFFFFu, x, o);
        if (lane == 0) g_bsum[b] = x;
    }
}

__global__ void k_scan2() {   // 1 block: scan 50 block sums
    if (threadIdx.x != 0) return;
    int run = 0;
    for (int b = 0; b < 50; b++) { g_boff[b] = run; run += g_bsum[b]; }
    g_off[NN] = run;
}

__global__ void k_scan3() {   // grid 50, block 1024: local scan + write offsets
    int b = blockIdx.x, t = threadIdx.x;
    int i = b * 1000 + t;
    int v = (t < 1000 && i < NN) ? g_deg[i] : 0;
    int lane = t & 31, wid = t >> 5;
    int incl = v;
#pragma unroll
    for (int o = 1; o < 32; o <<= 1) {
        int u = __shfl_up_sync(0xFFFFFFFFu, incl, o);
        if (lane >= o) incl += u;
    }
    __shared__ int wl[32];
    if (lane == 31) wl[wid] = incl;
    __syncthreads();
    if (wid == 0) {
        int x = wl[lane];
#pragma unroll
        for (int o = 1; o < 32; o <<= 1) {
            int u = __shfl_up_sync(0xFFFFFFFFu, x, o);
            if (lane >= o) x += u;
        }
        wl[lane] = x;
    }
    __syncthreads();
    int excl = incl - v + ((wid > 0) ? wl[wid - 1] : 0);
    if (t < 1000 && i < NN) {
        int off = g_boff[b] + excl;
        g_off[i] = off;
        g_cur[i] = off;
    }
}

__global__ void k_scatter(const int* __restrict__ ei) {
    int e = blockIdx.x * blockDim.x + threadIdx.x;
    if (e >= ET) return;
    int src, dst;
    if (e < EE) { src = clampN(ld_ei(ei, e)); dst = clampN(ld_ei(ei, EE + e)); }
    else        { src = e - EE;               dst = e - EE; }
    int pos = atomicAdd(&g_cur[dst], 1);
    if (pos >= 0 && pos < ET) g_srcS[pos] = src;
}

// ---------------------------------------------------------------------------
// Layer-1 algebraic path
// ---------------------------------------------------------------------------
__global__ void k_wsd(const float* __restrict__ W1, const float* __restrict__ a1s,
                      const float* __restrict__ a1d) {
    int t = threadIdx.x;
    if (t >= 88) return;
    int k = t / 8, h = t % 8;
    float ss = 0.f, sd = 0.f;
    const float* wrow = W1 + k * 1024 + h * 128;
    const float* asr  = a1s + h * 128;
    const float* adr  = a1d + h * 128;
    for (int c = 0; c < 128; c++) {
        float w = wrow[c];
        ss += w * asr[c];
        sd += w * adr[c];
    }
    g_ws[k * 8 + h] = ss;
    g_wd[k * 8 + h] = sd;
}

__global__ void k_alx(const float* __restrict__ x) {
    __shared__ float ws[88], wd[88];
    int t = threadIdx.x;
    if (t < 88) { ws[t] = g_ws[t]; wd[t] = g_wd[t]; }
    __syncthreads();
    int n = blockIdx.x * blockDim.x + t;
    if (n >= NN) return;
    float xv[11];
#pragma unroll
    for (int k = 0; k < 11; k++) xv[k] = x[n * 11 + k];
#pragma unroll
    for (int h = 0; h < 8; h++) {
        float ps = 0.f, pd = 0.f;
#pragma unroll
        for (int k = 0; k < 11; k++) {
            ps += xv[k] * ws[k * 8 + h];
            pd += xv[k] * wd[k * 8 + h];
        }
        g_als[n * 8 + h] = ps;
        g_ald[n * 8 + h] = pd;
    }
}

// softmax stats per (node, head)
template <int H>
__global__ void k_stats(const float* __restrict__ als, const float* __restrict__ ald,
                        float* __restrict__ emax, float* __restrict__ dinv) {
    int idx = blockIdx.x * blockDim.x + threadIdx.x;
    if (idx >= NN * H) return;
    int n = idx / H, hh = idx - n * H;
    float ad = ald[idx];
    int s0 = g_off[n], s1 = g_off[n + 1];
    float m = -FLT_MAX;
    for (int j = s0; j < s1; j++) {
        float e = als[g_srcS[j] * H + hh] + ad;
        e = fmaxf(e, 0.2f * e);
        m = fmaxf(m, e);
    }
    float ssum = 0.f;
    for (int j = s0; j < s1; j++) {
        float e = als[g_srcS[j] * H + hh] + ad;
        e = fmaxf(e, 0.2f * e);
        ssum += __expf(e - m);
    }
    emax[idx] = m;
    dinv[idx] = 1.f / (ssum + 1e-16f);
}

// z[n][h][k] = sum_e alpha_eh * x[src_e][k]   (thread per node)
__global__ void k_aggx(const float* __restrict__ x) {
    int n = blockIdx.x * blockDim.x + threadIdx.x;
    if (n >= NN) return;
    float z[88];
#pragma unroll
    for (int i = 0; i < 88; i++) z[i] = 0.f;
    float ad[8], em[8], dv[8];
#pragma unroll
    for (int h = 0; h < 8; h++) {
        ad[h] = g_ald[n * 8 + h];
        em[h] = g_emax[n * 8 + h];
        dv[h] = g_dinv[n * 8 + h];
    }
    int s0 = g_off[n], s1 = g_off[n + 1];
    for (int j = s0; j < s1; j++) {
        int s = g_srcS[j];
        float xs_[11];
#pragma unroll
        for (int k = 0; k < 11; k++) xs_[k] = x[s * 11 + k];
#pragma unroll
        for (int h = 0; h < 8; h++) {
            float e = g_als[s * 8 + h] + ad[h];
            e = fmaxf(e, 0.2f * e);
            float a = __expf(e - em[h]) * dv[h];
#pragma unroll
            for (int k = 0; k < 11; k++) z[h * 11 + k] += a * xs_[k];
        }
    }
#pragma unroll
    for (int i = 0; i < 88; i++) g_z[(size_t)n * 88 + i] = z[i];
}

// o1[n][h*128+c] = lrelu( z[n][h] . W1[:, h*128+c] + b1 )
__global__ __launch_bounds__(256) void k_proj(const float* __restrict__ W1,
                                              const float* __restrict__ b1,
                                              float* __restrict__ o1) {
    __shared__ float Wh[11][128];
    __shared__ float zt[64][11];
    int n0 = blockIdx.x * 64;
    int h = blockIdx.y;
    int t = threadIdx.x;
    for (int i = t; i < 11 * 128; i += 256) {
        int k = i >> 7, c = i & 127;
        Wh[k][c] = W1[k * 1024 + h * 128 + c];
    }
    for (int i = t; i < 64 * 11; i += 256) {
        int r = i / 11, k = i - r * 11;
        int n = n0 + r;
        zt[r][k] = (n < NN) ? g_z[(size_t)n * 88 + h * 11 + k] : 0.f;
    }
    __syncthreads();
    int c = t & 127;
    int r0 = (t >> 7) * 32;
    float bias = b1[h * 128 + c];
#pragma unroll 4
    for (int i = 0; i < 32; i++) {
        int r = r0 + i;
        int n = n0 + r;
        if (n >= NN) break;
        float acc = bias;
#pragma unroll
        for (int k = 0; k < 11; k++) acc += zt[r][k] * Wh[k][c];
        o1[(size_t)n * 1024 + h * 128 + c] = (acc > 0.f) ? acc : 0.01f * acc;
    }
}

// ---------------------------------------------------------------------------
// 3xTF32 tensor-core GEMM, cp.async double-buffered.
// C(Nrows x M) = A(Nrows x K) @ B(K x M). BM=128, BN=128, BK=32.
// Dynamic smem: As[2][128][36] + Bs[2][32][136]  (71680 B)
// ---------------------------------------------------------------------------
#define AP 36    // As pitch: banks (4g+tg)%32 unique -> conflict-free
#define BP 136   // Bs pitch: banks (8tg+g)%32 unique -> conflict-free
#define GEMM_SMEM ((2 * 128 * AP + 2 * 32 * BP) * 4)

__device__ __forceinline__ void mma_tf32(float* c, const uint32_t* a, const uint32_t* b) {
    asm volatile(
        "mma.sync.aligned.m16n8k8.row.col.f32.tf32.tf32.f32 "
        "{%0,%1,%2,%3}, {%4,%5,%6,%7}, {%8,%9}, {%0,%1,%2,%3};"
        : "+f"(c[0]), "+f"(c[1]), "+f"(c[2]), "+f"(c[3])
        : "r"(a[0]), "r"(a[1]), "r"(a[2]), "r"(a[3]), "r"(b[0]), "r"(b[1]));
}

__device__ __forceinline__ void split_tf32(float v, uint32_t& hi, uint32_t& lo) {
    uint32_t h;
    asm("cvt.rna.tf32.f32 %0, %1;" : "=r"(h) : "f"(v));
    float rem = v - __uint_as_float(h);
    asm("cvt.rna.tf32.f32 %0, %1;" : "=r"(lo) : "f"(rem));
    hi = h;
}

__device__ __forceinline__ void cp16(uint32_t dst, const void* src, int srcbytes) {
    asm volatile("cp.async.cg.shared.global [%0], [%1], 16, %2;"
                 :: "r"(dst), "l"(src), "r"(srcbytes));
}

__global__ __launch_bounds__(256) void k_sgemm_tc(const float* __restrict__ A,
                                                  const float* __restrict__ B,
                                                  float* __restrict__ C,
                                                  int Nrows, int K, int M) {
    extern __shared__ float smem[];
    float* AsBase = smem;                       // [2][128][AP]
    float* BsBase = smem + 2 * 128 * AP;        // [2][32][BP]

    int tid = threadIdx.x;
    int lane = tid & 31, warp = tid >> 5;
    int g = lane >> 2, tg = lane & 3;
    int rowBase = blockIdx.x * 128;
    int colBase = blockIdx.y * 128;
    int warpM = (warp & 1) * 64;
    int warpN = (warp >> 1) * 32;

    // loader assignments
    int am   = tid >> 1;                // 0..127 (A row within tile)
    int akb  = (tid & 1) * 16;          // 0 or 16 (A k base, 4 chunks of 4)
    bool avalid = (rowBase + am) < Nrows;
    const float* Abase = A + (size_t)(rowBase + am) * K + akb;
    uint32_t AsDst[2];
    AsDst[0] = (uint32_t)__cvta_generic_to_shared(AsBase + am * AP + akb);
    AsDst[1] = (uint32_t)__cvta_generic_to_shared(AsBase + 128 * AP + am * AP + akb);

    int brow = tid >> 3;                // 0..31
    int bcb  = (tid & 7) * 4;           // col base, 4 chunks stride 32
    const float* Bbase = B + (size_t)brow * M + colBase + bcb;
    uint32_t BsDst[2];
    BsDst[0] = (uint32_t)__cvta_generic_to_shared(BsBase + brow * BP + bcb);
    BsDst[1] = (uint32_t)__cvta_generic_to_shared(BsBase + 32 * BP + brow * BP + bcb);

    float acc[4][4][4];
#pragma unroll
    for (int mt = 0; mt < 4; mt++)
#pragma unroll
        for (int nt = 0; nt < 4; nt++)
#pragma unroll
            for (int i = 0; i < 4; i++) acc[mt][nt][i] = 0.f;

    const int NT = K >> 5;   // tiles of 32

    // issue tile t into buffer buf
    auto issue = [&](int t, int buf) {
        const float* ap = Abase + t * 32;
        int ab = avalid ? 16 : 0;
#pragma unroll
        for (int i = 0; i < 4; i++)
            cp16(AsDst[buf] + i * 16, ap + i * 4, ab);
        const float* bp = Bbase + (size_t)t * 32 * M;
#pragma unroll
        for (int i = 0; i < 4; i++)
            cp16(BsDst[buf] + i * 32 * 4, bp + i * 32, 16);
    };

    issue(0, 0);
    asm volatile("cp.async.commit_group;");

    for (int t = 0; t < NT; t++) {
        if (t + 1 < NT) issue(t + 1, (t + 1) & 1);
        asm volatile("cp.async.commit_group;");
        asm volatile("cp.async.wait_group 1;");
        __syncthreads();

        const float* As = AsBase + (t & 1) * 128 * AP;
        const float* Bs = BsBase + (t & 1) * 32 * BP;

#pragma unroll
        for (int kk = 0; kk < 32; kk += 8) {
            uint32_t ah[4][4], al[4][4], bh[4][2], bl[4][2];
#pragma unroll
            for (int mt = 0; mt < 4; mt++) {
                int r0 = warpM + mt * 16 + g;
                float a0 = As[r0 * AP + kk + tg];
                float a1 = As[(r0 + 8) * AP + kk + tg];
                float a2 = As[r0 * AP + kk + tg + 4];
                float a3 = As[(r0 + 8) * AP + kk + tg + 4];
                split_tf32(a0, ah[mt][0], al[mt][0]);
                split_tf32(a1, ah[mt][1], al[mt][1]);
                split_tf32(a2, ah[mt][2], al[mt][2]);
                split_tf32(a3, ah[mt][3], al[mt][3]);
            }
#pragma unroll
            for (int nt = 0; nt < 4; nt++) {
                int c0 = warpN + nt * 8 + g;
                float b0 = Bs[(kk + tg) * BP + c0];
                float b1 = Bs[(kk + tg + 4) * BP + c0];
                split_tf32(b0, bh[nt][0], bl[nt][0]);
                split_tf32(b1, bh[nt][1], bl[nt][1]);
            }
#pragma unroll
            for (int mt = 0; mt < 4; mt++)
#pragma unroll
                for (int nt = 0; nt < 4; nt++) {
                    mma_tf32(acc[mt][nt], ah[mt], bh[nt]);
                    mma_tf32(acc[mt][nt], ah[mt], bl[nt]);
                    mma_tf32(acc[mt][nt], al[mt], bh[nt]);
                }
        }
        __syncthreads();
    }

#pragma unroll
    for (int mt = 0; mt < 4; mt++) {
#pragma unroll
        for (int nt = 0; nt < 4; nt++) {
            int r = rowBase + warpM + mt * 16 + g;
            int cc = colBase + warpN + nt * 8 + tg * 2;
            if (r < Nrows)
                *(float2*)&C[(size_t)r * M + cc] = make_float2(acc[mt][nt][0], acc[mt][nt][1]);
            if (r + 8 < Nrows)
                *(float2*)&C[(size_t)(r + 8) * M + cc] = make_float2(acc[mt][nt][2], acc[mt][nt][3]);
        }
    }
}

// ---------------------------------------------------------------------------
// al_s / al_d per (node, head) from dense h
// ---------------------------------------------------------------------------
template <int OUT, int C, int H>
__global__ void k_al(const float* __restrict__ h, const float* __restrict__ as,
                     const float* __restrict__ ad, float* __restrict__ als,
                     float* __restrict__ ald) {
    constexpr int R = C / 32;
    int n = blockIdx.x, t = threadIdx.x;   // blockDim == H*32
    const float* hp = h + (size_t)n * OUT + t * R;
    float ps = 0.f, pd = 0.f;
#pragma unroll
    for (int j = 0; j < R; j++) {
        float v = hp[j];
        ps += v * as[t * R + j];
        pd += v * ad[t * R + j];
    }
#pragma unroll
    for (int o = 16; o > 0; o >>= 1) {
        ps += __shfl_down_sync(0xFFFFFFFFu, ps, o);
        pd += __shfl_down_sync(0xFFFFFFFFu, pd, o);
    }
    if ((t & 31) == 0) {
        int w = t >> 5;
        als[n * H + w] = ps;
        ald[n * H + w] = pd;
    }
}

// ---------------------------------------------------------------------------
// Aggregation: out[n] = lrelu_{0.01}( sum_e alpha * h[src] + bias )
// ---------------------------------------------------------------------------
template <int OUT, int H, int C>
__global__ void k_agg(const float* __restrict__ h, const float* __restrict__ als,
                      const float* __restrict__ ald, const float* __restrict__ emax,
                      const float* __restrict__ dinv, const float* __restrict__ bias,
                      float* __restrict__ out) {
    constexpr int T = (OUT < 256) ? OUT : 256;
    constexpr int R = OUT / T;
    __shared__ int   ssrc[32];
    __shared__ float salpha[32 * H];
    int n = blockIdx.x, t = threadIdx.x;
    int myhead = (t * R) / C;

    float acc[R];
#pragma unroll
    for (int j = 0; j < R; j++) acc[j] = 0.f;

    int s0 = g_off[n], s1 = g_off[n + 1];
    for (int e0 = s0; e0 < s1; e0 += 32) {
        int cs = min(32, s1 - e0);
        if (t < cs) ssrc[t] = g_srcS[e0 + t];
        __syncthreads();
        if (t < cs * H) {
            int i = t / H, hh = t - i * H;
            float e = als[ssrc[i] * H + hh] + ald[n * H + hh];
            e = fmaxf(e, 0.2f * e);
            salpha[i * H + hh] = __expf(e - emax[n * H + hh]) * dinv[n * H + hh];
        }
        __syncthreads();
        for (int i = 0; i < cs; i++) {
            float a = salpha[i * H + myhead];
            const float* hp = h + (size_t)ssrc[i] * OUT + t * R;
            if constexpr (R == 2) {
                float2 v = *(const float2*)hp;
                acc[0] += a * v.x; acc[1] += a * v.y;
            } else {
                acc[0] += a * hp[0];
            }
        }
        __syncthreads();
    }
#pragma unroll
    for (int j = 0; j < R; j++) {
        float v = acc[j] + bias[t * R + j];
        out[(size_t)n * OUT + t * R + j] = (v > 0.f) ? v : 0.01f * v;
    }
}

// ---------------------------------------------------------------------------
// Pooling + head
// ---------------------------------------------------------------------------
__device__ __forceinline__ int lower_bound_b(const int* __restrict__ b, int val) {
    int lo = 0, hi = NN;
    while (lo < hi) {
        int mid = (lo + hi) >> 1;
        if (ld_b(b, mid) < val) lo = mid + 1; else hi = mid;
    }
    return lo;
}

__global__ void k_poolseg(const int* __restrict__ batch, const float* __restrict__ o3,
                          const float* __restrict__ Wout, const float* __restrict__ bout,
                          float* __restrict__ out) {
    int gph = blockIdx.x, t = threadIdx.x;   // 128 threads
    int lo = lower_bound_b(batch, gph);
    int hi = lower_bound_b(batch, gph + 1);
    float s = 0.f;
    for (int n = lo; n < hi; n++) s += o3[(size_t)n * 128 + t];
    float cnt = fmaxf((float)(hi - lo), 1.f);
    float v = (s / cnt) * Wout[t];
#pragma unroll
    for (int o = 16; o > 0; o >>= 1) v += __shfl_down_sync(0xFFFFFFFFu, v, o);
    __shared__ float red[4];
    if ((t & 31) == 0) red[t >> 5] = v;
    __syncthreads();
    if (t == 0) out[gph] = red[0] + red[1] + red[2] + red[3] + bout[0];
}

// ---------------------------------------------------------------------------
// Launch
// ---------------------------------------------------------------------------
extern "C" void kernel_launch(void* const* d_in, const int* in_sizes, int n_in,
                              void* d_out, int out_size) {
    int ix = 0, iei = 1, ib = 2, iW1 = 3, ia1s = 4, ia1d = 5, ib1 = 6,
        iW2 = 7, ia2s = 8, ia2d = 9, ib2 = 10, iW3 = 11, ia3s = 12,
        ia3d = 13, ib3 = 14, iWout = 15, ibout = 16;
    {
        int jx = -1, jei = -1, jb = -1, jW1 = -1, jW2 = -1, jW3 = -1, jbout = -1;
        int j1024[3], n1024 = 0;
        int j512[3],  n512 = 0;
        int j128[4],  n128 = 0;
        bool clean = true;
        for (int i = 0; i < n_in; i++) {
            int s = in_sizes[i];
            if      (s == 550000) { if (jx >= 0) clean = false; jx = i; }
            else if (s == 500000) { if (jei >= 0) clean = false; jei = i; }
            else if (s == 50000)  { if (jb >= 0) clean = false; jb = i; }
            else if (s == 11264)  { if (jW1 >= 0) clean = false; jW1 = i; }
            else if (s == 524288) { if (jW2 >= 0) clean = false; jW2 = i; }
            else if (s == 65536)  { if (jW3 >= 0) clean = false; jW3 = i; }
            else if (s == 1024)   { if (n1024 < 3) j1024[n1024] = i; n1024++; }
            else if (s == 512)    { if (n512  < 3) j512[n512]   = i; n512++; }
            else if (s == 128)    { if (n128  < 4) j128[n128]   = i; n128++; }
            else if (s == 1)      { if (jbout >= 0) clean = false; jbout = i; }
            else clean = false;
        }
        if (clean && jx >= 0 && jei >= 0 && jb >= 0 && jW1 >= 0 && jW2 >= 0 &&
            jW3 >= 0 && jbout >= 0 && n1024 == 3 && n512 == 3 && n128 == 4) {
            ix = jx; iei = jei; ib = jb; iW1 = jW1; iW2 = jW2; iW3 = jW3;
            ia1s = j1024[0]; ia1d = j1024[1]; ib1 = j1024[2];
            ia2s = j512[0];  ia2d = j512[1];  ib2 = j512[2];
            ia3s = j128[0];  ia3d = j128[1];  ib3 = j128[2]; iWout = j128[3];
            ibout = jbout;
        }
    }

    const float* x    = (const float*)d_in[ix];
    const int*   ei   = (const int*)d_in[iei];
    const int*   batch= (const int*)d_in[ib];
    const float* W1   = (const float*)d_in[iW1];
    const float* a1s  = (const float*)d_in[ia1s];
    const float* a1d  = (const float*)d_in[ia1d];
    const float* b1   = (const float*)d_in[ib1];
    const float* W2   = (const float*)d_in[iW2];
    const float* a2s  = (const float*)d_in[ia2s];
    const float* a2d  = (const float*)d_in[ia2d];
    const float* b2   = (const float*)d_in[ib2];
    const float* W3   = (const float*)d_in[iW3];
    const float* a3s  = (const float*)d_in[ia3s];
    const float* a3d  = (const float*)d_in[ia3d];
    const float* b3   = (const float*)d_in[ib3];
    const float* Wout = (const float*)d_in[iWout];
    const float* bout = (const float*)d_in[ibout];
    float* out = (float*)d_out;

    float* P = nullptr;   cudaGetSymbolAddress((void**)&P, g_P);
    float* Q = nullptr;   cudaGetSymbolAddress((void**)&Q, g_Q);
    float* als = nullptr; cudaGetSymbolAddress((void**)&als, g_als);
    float* ald = nullptr; cudaGetSymbolAddress((void**)&ald, g_ald);
    float* emax = nullptr; cudaGetSymbolAddress((void**)&emax, g_emax);
    float* dinv = nullptr; cudaGetSymbolAddress((void**)&dinv, g_dinv);

    static bool attr_set = false;
    if (!attr_set) {
        cudaFuncSetAttribute(k_sgemm_tc, cudaFuncAttributeMaxDynamicSharedMemorySize,
                             GEMM_SMEM);
        attr_set = true;
    }

    // dtype detection + CSR build
    k_detect<<<1, 1024>>>(ei, batch);
    k_zero_deg<<<(NN + 255) / 256, 256>>>();
    k_count<<<(ET + 255) / 256, 256>>>(ei);
    k_scan1<<<50, 1024>>>();
    k_scan2<<<1, 32>>>();
    k_scan3<<<50, 1024>>>();
    k_scatter<<<(ET + 255) / 256, 256>>>(ei);

    // ---- Layer 1 (algebraic): o1 = Q ----
    k_wsd<<<1, 128>>>(W1, a1s, a1d);
    k_alx<<<(NN + 255) / 256, 256>>>(x);
    k_stats<8><<<(NN * 8 + 255) / 256, 256>>>(als, ald, emax, dinv);
    k_aggx<<<(NN + 127) / 128, 128>>>(x);
    {
        dim3 grid((NN + 63) / 64, 8);
        k_proj<<<grid, 256>>>(W1, b1, Q);
    }

    // ---- Layer 2: h2 = Q @ W2 (3xTF32 TC, cp.async), agg -> Q ----
    {
        dim3 grid((NN + 127) / 128, 4);
        k_sgemm_tc<<<grid, 256, GEMM_SMEM>>>(Q, W2, P, NN, 1024, 512);
        k_al<512, 64, 8><<<NN, 256>>>(P, a2s, a2d, als, ald);
        k_stats<8><<<(NN * 8 + 255) / 256, 256>>>(als, ald, emax, dinv);
        k_agg<512, 8, 64><<<NN, 256>>>(P, als, ald, emax, dinv, b2, Q);
    }

    // ---- Layer 3: h3 = Q @ W3 (3xTF32 TC, cp.async), agg -> Q ----
    {
        dim3 grid((NN + 127) / 128, 1);
        k_sgemm_tc<<<grid, 256, GEMM_SMEM>>>(Q, W3, P, NN, 512, 128);
        k_al<128, 32, 4><<<NN, 128>>>(P, a3s, a3d, als, ald);
        k_stats<4><<<(NN * 4 + 255) / 256, 256>>>(als, ald, emax, dinv);
        k_agg<128, 4, 32><<<NN, 128>>>(P, als, ald, emax, dinv, b3, Q);
    }

    // ---- Pool + head ----
    k_poolseg<<<NG, 128>>>(batch, Q, Wout, bout, out);
}

// round 9
// speedup vs baseline: 1.7412x; 1.3001x over previous
#include <cuda_runtime.h>
#include <cuda_bf16.h>
#include <float.h>
#include <stdint.h>

#define NN   50000
#define EE   250000
#define ET   300000
#define NG   64

// ---------------------------------------------------------------------------
// Device scratch
// ---------------------------------------------------------------------------
__device__ __align__(16) float    g_P[(size_t)NN * 512];    // h2 / h3 (fp32)
__device__ __align__(16) uint32_t g_Qh[(size_t)NN * 512];   // o1/o2 bf16-hi packed; o3 fp32
__device__ __align__(16) uint32_t g_Ql[(size_t)NN * 512];   // o1/o2 bf16-lo packed
__device__ __align__(16) float    g_z[(size_t)NN * 88];     // layer-1 aggregated x

__device__ __align__(16) uint32_t g_B2h[512 * 512];   // W2 packed hi  [K/2][M]
__device__ __align__(16) uint32_t g_B2l[512 * 512];
__device__ __align__(16) uint32_t g_B3h[256 * 128];
__device__ __align__(16) uint32_t g_B3l[256 * 128];

__device__ float g_als[NN * 8];
__device__ float g_ald[NN * 8];
__device__ float g_emax[NN * 8];
__device__ float g_dinv[NN * 8];
__device__ float g_ws[11 * 8];
__device__ float g_wd[11 * 8];

__device__ int   g_srcS[ET];
__device__ int   g_deg[NN];
__device__ int   g_off[NN + 1];
__device__ int   g_cur[NN];
__device__ int   g_bsum[64];
__device__ int   g_boff[64];

__device__ int g_ei64;
__device__ int g_b64;

__device__ __forceinline__ int clampN(int v) {
    return (v < 0) ? 0 : ((v >= NN) ? NN - 1 : v);
}

// bf16 hi/lo split of two adjacent-k values, packed (lo halfword = even k)
__device__ __forceinline__ void split_pack(float v0, float v1, uint32_t& ph, uint32_t& pl) {
    __nv_bfloat16 h0 = __float2bfloat16(v0);
    __nv_bfloat16 h1 = __float2bfloat16(v1);
    float r0 = v0 - __bfloat162float(h0);
    float r1 = v1 - __bfloat162float(h1);
    __nv_bfloat16 l0 = __float2bfloat16(r0);
    __nv_bfloat16 l1 = __float2bfloat16(r1);
    __nv_bfloat162 H = __halves2bfloat162(h0, h1);
    __nv_bfloat162 L = __halves2bfloat162(l0, l1);
    ph = *reinterpret_cast<uint32_t*>(&H);
    pl = *reinterpret_cast<uint32_t*>(&L);
}

// ---------------------------------------------------------------------------
// Parallel dtype detection (int32 vs int64 index inputs)
// ---------------------------------------------------------------------------
__global__ void k_detect(const int* __restrict__ ei, const int* __restrict__ batch) {
    int t = threadIdx.x;   // 1024 threads
    int ok1 = (ei[2 * t + 1] == 0);
    int idx = NN - 1024 + t;
    int ok2 = ((idx & 1) == 0) || (batch[idx] == 0);
    int a1 = __syncthreads_and(ok1);
    int a2 = __syncthreads_and(ok2);
    if (t == 0) { g_ei64 = a1; g_b64 = a2; }
}

__device__ __forceinline__ int ld_ei(const int* __restrict__ ei, int i) {
    return g_ei64 ? ei[2 * i] : ei[i];
}
__device__ __forceinline__ int ld_b(const int* __restrict__ b, int i) {
    return g_b64 ? b[2 * i] : b[i];
}

// ---------------------------------------------------------------------------
// CSR build
// ---------------------------------------------------------------------------
__global__ void k_zero_deg() {
    int i = blockIdx.x * blockDim.x + threadIdx.x;
    if (i < NN) g_deg[i] = 0;
}

__global__ void k_count(const int* __restrict__ ei) {
    int e = blockIdx.x * blockDim.x + threadIdx.x;
    if (e >= ET) return;
    int dst = (e < EE) ? clampN(ld_ei(ei, EE + e)) : (e - EE);
    atomicAdd(&g_deg[dst], 1);
}

__global__ void k_scan1() {   // grid 50, block 1024
    int b = blockIdx.x, t = threadIdx.x;
    int i = b * 1000 + t;
    int v = (t < 1000 && i < NN) ? g_deg[i] : 0;
#pragma unroll
    for (int o = 16; o > 0; o >>= 1) v += __shfl_down_sync(0xFFFFFFFFu, v, o);
    __shared__ int w[32];
    int lane = t & 31, wid = t >> 5;
    if (lane == 0) w[wid] = v;
    __syncthreads();
    if (wid == 0) {
        int x = w[lane];
#pragma unroll
        for (int o = 16; o > 0; o >>= 1) x += __shfl_down_sync(0xFFFFFFFFu, x, o);
        if (lane == 0) g_bsum[b] = x;
    }
}

__global__ void k_scan2() {
    if (threadIdx.x != 0) return;
    int run = 0;
    for (int b = 0; b < 50; b++) { g_boff[b] = run; run += g_bsum[b]; }
    g_off[NN] = run;
}

__global__ void k_scan3() {
    int b = blockIdx.x, t = threadIdx.x;
    int i = b * 1000 + t;
    int v = (t < 1000 && i < NN) ? g_deg[i] : 0;
    int lane = t & 31, wid = t >> 5;
    int incl = v;
#pragma unroll
    for (int o = 1; o < 32; o <<= 1) {
        int u = __shfl_up_sync(0xFFFFFFFFu, incl, o);
        if (lane >= o) incl += u;
    }
    __shared__ int wl[32];
    if (lane == 31) wl[wid] = incl;
    __syncthreads();
    if (wid == 0) {
        int x = wl[lane];
#pragma unroll
        for (int o = 1; o < 32; o <<= 1) {
            int u = __shfl_up_sync(0xFFFFFFFFu, x, o);
            if (lane >= o) x += u;
        }
        wl[lane] = x;
    }
    __syncthreads();
    int excl = incl - v + ((wid > 0) ? wl[wid - 1] : 0);
    if (t < 1000 && i < NN) {
        int off = g_boff[b] + excl;
        g_off[i] = off;
        g_cur[i] = off;
    }
}

__global__ void k_scatter(const int* __restrict__ ei) {
    int e = blockIdx.x * blockDim.x + threadIdx.x;
    if (e >= ET) return;
    int src, dst;
    if (e < EE) { src = clampN(ld_ei(ei, e)); dst = clampN(ld_ei(ei, EE + e)); }
    else        { src = e - EE;               dst = e - EE; }
    int pos = atomicAdd(&g_cur[dst], 1);
    if (pos >= 0 && pos < ET) g_srcS[pos] = src;
}

// ---------------------------------------------------------------------------
// Weight prep: pack W (KxM fp32, row-major) into hi/lo bf16 pairs [K/2][M]
// ---------------------------------------------------------------------------
__global__ void k_wprep(const float* __restrict__ W, uint32_t* __restrict__ Bh,
                        uint32_t* __restrict__ Bl, int K2, int M) {
    int idx = blockIdx.x * blockDim.x + threadIdx.x;
    if (idx >= K2 * M) return;
    int k2 = idx / M, n = idx - k2 * M;
    float a0 = W[(size_t)(2 * k2) * M + n];
    float a1 = W[(size_t)(2 * k2 + 1) * M + n];
    uint32_t ph, pl;
    split_pack(a0, a1, ph, pl);
    Bh[idx] = ph;
    Bl[idx] = pl;
}

// ---------------------------------------------------------------------------
// Layer-1 algebraic path
// ---------------------------------------------------------------------------
__global__ void k_wsd(const float* __restrict__ W1, const float* __restrict__ a1s,
                      const float* __restrict__ a1d) {
    int t = threadIdx.x;
    if (t >= 88) return;
    int k = t / 8, h = t % 8;
    float ss = 0.f, sd = 0.f;
    const float* wrow = W1 + k * 1024 + h * 128;
    const float* asr  = a1s + h * 128;
    const float* adr  = a1d + h * 128;
    for (int c = 0; c < 128; c++) {
        float w = wrow[c];
        ss += w * asr[c];
        sd += w * adr[c];
    }
    g_ws[k * 8 + h] = ss;
    g_wd[k * 8 + h] = sd;
}

__global__ void k_alx(const float* __restrict__ x) {
    __shared__ float ws[88], wd[88];
    int t = threadIdx.x;
    if (t < 88) { ws[t] = g_ws[t]; wd[t] = g_wd[t]; }
    __syncthreads();
    int n = blockIdx.x * blockDim.x + t;
    if (n >= NN) return;
    float xv[11];
#pragma unroll
    for (int k = 0; k < 11; k++) xv[k] = x[n * 11 + k];
#pragma unroll
    for (int h = 0; h < 8; h++) {
        float ps = 0.f, pd = 0.f;
#pragma unroll
        for (int k = 0; k < 11; k++) {
            ps += xv[k] * ws[k * 8 + h];
            pd += xv[k] * wd[k * 8 + h];
        }
        g_als[n * 8 + h] = ps;
        g_ald[n * 8 + h] = pd;
    }
}

template <int H>
__global__ void k_stats(const float* __restrict__ als, const float* __restrict__ ald,
                        float* __restrict__ emax, float* __restrict__ dinv) {
    int idx = blockIdx.x * blockDim.x + threadIdx.x;
    if (idx >= NN * H) return;
    int n = idx / H, hh = idx - n * H;
    float ad = ald[idx];
    int s0 = g_off[n], s1 = g_off[n + 1];
    float m = -FLT_MAX;
    for (int j = s0; j < s1; j++) {
        float e = als[g_srcS[j] * H + hh] + ad;
        e = fmaxf(e, 0.2f * e);
        m = fmaxf(m, e);
    }
    float ssum = 0.f;
    for (int j = s0; j < s1; j++) {
        float e = als[g_srcS[j] * H + hh] + ad;
        e = fmaxf(e, 0.2f * e);
        ssum += __expf(e - m);
    }
    emax[idx] = m;
    dinv[idx] = 1.f / (ssum + 1e-16f);
}

__global__ void k_aggx(const float* __restrict__ x) {
    int n = blockIdx.x * blockDim.x + threadIdx.x;
    if (n >= NN) return;
    float z[88];
#pragma unroll
    for (int i = 0; i < 88; i++) z[i] = 0.f;
    float ad[8], em[8], dv[8];
#pragma unroll
    for (int h = 0; h < 8; h++) {
        ad[h] = g_ald[n * 8 + h];
        em[h] = g_emax[n * 8 + h];
        dv[h] = g_dinv[n * 8 + h];
    }
    int s0 = g_off[n], s1 = g_off[n + 1];
    for (int j = s0; j < s1; j++) {
        int s = g_srcS[j];
        float xs_[11];
#pragma unroll
        for (int k = 0; k < 11; k++) xs_[k] = x[s * 11 + k];
#pragma unroll
        for (int h = 0; h < 8; h++) {
            float e = g_als[s * 8 + h] + ad[h];
            e = fmaxf(e, 0.2f * e);
            float a = __expf(e - em[h]) * dv[h];
#pragma unroll
            for (int k = 0; k < 11; k++) z[h * 11 + k] += a * xs_[k];
        }
    }
#pragma unroll
    for (int i = 0; i < 88; i++) g_z[(size_t)n * 88 + i] = z[i];
}

// o1 projection; emits bf16 hi/lo packed pairs (channels 2c, 2c+1)
__global__ __launch_bounds__(256) void k_proj(const float* __restrict__ W1,
                                              const float* __restrict__ b1,
                                              uint32_t* __restrict__ oh,
                                              uint32_t* __restrict__ ol) {
    __shared__ float Wh[11][128];
    __shared__ float zt[64][11];
    int n0 = blockIdx.x * 64;
    int h = blockIdx.y;
    int t = threadIdx.x;
    for (int i = t; i < 11 * 128; i += 256) {
        int k = i >> 7, c = i & 127;
        Wh[k][c] = W1[k * 1024 + h * 128 + c];
    }
    for (int i = t; i < 64 * 11; i += 256) {
        int r = i / 11, k = i - r * 11;
        int n = n0 + r;
        zt[r][k] = (n < NN) ? g_z[(size_t)n * 88 + h * 11 + k] : 0.f;
    }
    __syncthreads();
    int c = t & 63;          // channel pair index
    int rg = t >> 6;         // 0..3
    float bias0 = b1[h * 128 + 2 * c];
    float bias1 = b1[h * 128 + 2 * c + 1];
#pragma unroll 4
    for (int i = 0; i < 16; i++) {
        int r = rg * 16 + i;
        int n = n0 + r;
        if (n >= NN) break;
        float a0 = bias0, a1 = bias1;
#pragma unroll
        for (int k = 0; k < 11; k++) {
            float zz = zt[r][k];
            a0 += zz * Wh[k][2 * c];
            a1 += zz * Wh[k][2 * c + 1];
        }
        a0 = (a0 > 0.f) ? a0 : 0.01f * a0;
        a1 = (a1 > 0.f) ? a1 : 0.01f * a1;
        uint32_t ph, pl;
        split_pack(a0, a1, ph, pl);
        oh[(size_t)n * 512 + h * 64 + c] = ph;
        ol[(size_t)n * 512 + h * 64 + c] = pl;
    }
}

// ---------------------------------------------------------------------------
// bf16x3 tensor-core GEMM (pre-split operands), cp.async double-buffered.
// C = A @ B; A packed pairs [Nrows][K/2] u32, B packed pairs [K/2][M] u32.
// BM=128, BN=128, BK=32 (=16 u32).
// ---------------------------------------------------------------------------
#define AP2 20    // A smem pitch (u32): banks (20g+tg)%32 distinct
#define BP2 136   // B smem pitch (u32): banks (8tg+g)%32 distinct
#define GEMM_SMEM ((2 * 128 * AP2 * 2 + 2 * 16 * BP2 * 2) * 4)

__device__ __forceinline__ void mma_bf16(float* c, const uint32_t* a, const uint32_t* b) {
    asm volatile(
        "mma.sync.aligned.m16n8k16.row.col.f32.bf16.bf16.f32 "
        "{%0,%1,%2,%3}, {%4,%5,%6,%7}, {%8,%9}, {%0,%1,%2,%3};"
        : "+f"(c[0]), "+f"(c[1]), "+f"(c[2]), "+f"(c[3])
        : "r"(a[0]), "r"(a[1]), "r"(a[2]), "r"(a[3]), "r"(b[0]), "r"(b[1]));
}

__device__ __forceinline__ void cp16(uint32_t dst, const void* src, int srcbytes) {
    asm volatile("cp.async.cg.shared.global [%0], [%1], 16, %2;"
                 :: "r"(dst), "l"(src), "r"(srcbytes));
}

__global__ __launch_bounds__(256) void k_gemm_bf16(const uint32_t* __restrict__ Ahp,
                                                   const uint32_t* __restrict__ Alp,
                                                   const uint32_t* __restrict__ Bhp,
                                                   const uint32_t* __restrict__ Blp,
                                                   float* __restrict__ C,
                                                   int Nrows, int K, int M) {
    extern __shared__ uint32_t smem[];
    uint32_t* Ash = smem;                            // [2][128][AP2]
    uint32_t* Asl = Ash + 2 * 128 * AP2;
    uint32_t* Bsh = Asl + 2 * 128 * AP2;             // [2][16][BP2]
    uint32_t* Bsl = Bsh + 2 * 16 * BP2;

    int tid = threadIdx.x;
    int lane = tid & 31, warp = tid >> 5;
    int g = lane >> 2, tg = lane & 3;
    int rowBase = blockIdx.x * 128;
    int colBase = blockIdx.y * 128;
    int warpM = (warp & 1) * 64;
    int warpN = (warp >> 1) * 32;
    int K2 = K >> 1;

    // loader assignments
    int am  = tid >> 1;             // A row 0..127
    int ak8 = (tid & 1) * 8;        // u32 col 0 or 8
    bool avalid = (rowBase + am) < Nrows;
    const uint32_t* Ah_src = Ahp + (size_t)(rowBase + am) * K2 + ak8;
    const uint32_t* Al_src = Alp + (size_t)(rowBase + am) * K2 + ak8;
    uint32_t AhD[2], AlD[2];
    AhD[0] = (uint32_t)__cvta_generic_to_shared(Ash + am * AP2 + ak8);
    AhD[1] = AhD[0] + 128 * AP2 * 4;
    AlD[0] = (uint32_t)__cvta_generic_to_shared(Asl + am * AP2 + ak8);
    AlD[1] = AlD[0] + 128 * AP2 * 4;

    int bk2 = tid >> 4;             // 0..15
    int bn8 = (tid & 15) * 8;       // u32 col
    const uint32_t* Bh_src = Bhp + (size_t)bk2 * M + colBase + bn8;
    const uint32_t* Bl_src = Blp + (size_t)bk2 * M + colBase + bn8;
    uint32_t BhD[2], BlD[2];
    BhD[0] = (uint32_t)__cvta_generic_to_shared(Bsh + bk2 * BP2 + bn8);
    BhD[1] = BhD[0] + 16 * BP2 * 4;
    BlD[0] = (uint32_t)__cvta_generic_to_shared(Bsl + bk2 * BP2 + bn8);
    BlD[1] = BlD[0] + 16 * BP2 * 4;

    float acc[4][4][4];
#pragma unroll
    for (int mt = 0; mt < 4; mt++)
#pragma unroll
        for (int nt = 0; nt < 4; nt++)
#pragma unroll
            for (int i = 0; i < 4; i++) acc[mt][nt][i] = 0.f;

    const int NT = K >> 5;

    auto issue = [&](int t, int buf) {
        int ab = avalid ? 16 : 0;
        cp16(AhD[buf] + 0,  Ah_src + t * 16 + 0, ab);
        cp16(AhD[buf] + 16, Ah_src + t * 16 + 4, ab);
        cp16(AlD[buf] + 0,  Al_src + t * 16 + 0, ab);
        cp16(AlD[buf] + 16, Al_src + t * 16 + 4, ab);
        const uint32_t* bh = Bh_src + (size_t)t * 16 * M;
        const uint32_t* bl = Bl_src + (size_t)t * 16 * M;
        cp16(BhD[buf] + 0,  bh + 0, 16);
        cp16(BhD[buf] + 16, bh + 4, 16);
        cp16(BlD[buf] + 0,  bl + 0, 16);
        cp16(BlD[buf] + 16, bl + 4, 16);
    };

    issue(0, 0);
    asm volatile("cp.async.commit_group;");

    for (int t = 0; t < NT; t++) {
        if (t + 1 < NT) issue(t + 1, (t + 1) & 1);
        asm volatile("cp.async.commit_group;");
        asm volatile("cp.async.wait_group 1;");
        __syncthreads();

        const uint32_t* As_h = Ash + (t & 1) * 128 * AP2;
        const uint32_t* As_l = Asl + (t & 1) * 128 * AP2;
        const uint32_t* Bs_h = Bsh + (t & 1) * 16 * BP2;
        const uint32_t* Bs_l = Bsl + (t & 1) * 16 * BP2;

#pragma unroll
        for (int kk = 0; kk < 2; kk++) {       // two k16 steps per BK32
            int k2b = kk * 8;
            uint32_t ah[4][4], al[4][4];
#pragma unroll
            for (int mt = 0; mt < 4; mt++) {
                int r0 = warpM + mt * 16 + g;
                ah[mt][0] = As_h[r0 * AP2 + k2b + tg];
                ah[mt][1] = As_h[(r0 + 8) * AP2 + k2b + tg];
                ah[mt][2] = As_h[r0 * AP2 + k2b + 4 + tg];
                ah[mt][3] = As_h[(r0 + 8) * AP2 + k2b + 4 + tg];
                al[mt][0] = As_l[r0 * AP2 + k2b + tg];
                al[mt][1] = As_l[(r0 + 8) * AP2 + k2b + tg];
                al[mt][2] = As_l[r0 * AP2 + k2b + 4 + tg];
                al[mt][3] = As_l[(r0 + 8) * AP2 + k2b + 4 + tg];
            }
#pragma unroll
            for (int nt = 0; nt < 4; nt++) {
                int c0 = warpN + nt * 8 + g;
                uint32_t bh[2], bl[2];
                bh[0] = Bs_h[(k2b + tg) * BP2 + c0];
                bh[1] = Bs_h[(k2b + 4 + tg) * BP2 + c0];
                bl[0] = Bs_l[(k2b + tg) * BP2 + c0];
                bl[1] = Bs_l[(k2b + 4 + tg) * BP2 + c0];
#pragma unroll
                for (int mt = 0; mt < 4; mt++) {
                    mma_bf16(acc[mt][nt], ah[mt], bh);
                    mma_bf16(acc[mt][nt], ah[mt], bl);
                    mma_bf16(acc[mt][nt], al[mt], bh);
                }
            }
        }
        __syncthreads();
    }

#pragma unroll
    for (int mt = 0; mt < 4; mt++) {
#pragma unroll
        for (int nt = 0; nt < 4; nt++) {
            int r = rowBase + warpM + mt * 16 + g;
            int cc = colBase + warpN + nt * 8 + tg * 2;
            if (r < Nrows)
                *(float2*)&C[(size_t)r * M + cc] = make_float2(acc[mt][nt][0], acc[mt][nt][1]);
            if (r + 8 < Nrows)
                *(float2*)&C[(size_t)(r + 8) * M + cc] = make_float2(acc[mt][nt][2], acc[mt][nt][3]);
        }
    }
}

// ---------------------------------------------------------------------------
// al_s / al_d per (node, head) from dense h
// ---------------------------------------------------------------------------
template <int OUT, int C, int H>
__global__ void k_al(const float* __restrict__ h, const float* __restrict__ as,
                     const float* __restrict__ ad, float* __restrict__ als,
                     float* __restrict__ ald) {
    constexpr int R = C / 32;
    int n = blockIdx.x, t = threadIdx.x;
    const float* hp = h + (size_t)n * OUT + t * R;
    float ps = 0.f, pd = 0.f;
#pragma unroll
    for (int j = 0; j < R; j++) {
        float v = hp[j];
        ps += v * as[t * R + j];
        pd += v * ad[t * R + j];
    }
#pragma unroll
    for (int o = 16; o > 0; o >>= 1) {
        ps += __shfl_down_sync(0xFFFFFFFFu, ps, o);
        pd += __shfl_down_sync(0xFFFFFFFFu, pd, o);
    }
    if ((t & 31) == 0) {
        int w = t >> 5;
        als[n * H + w] = ps;
        ald[n * H + w] = pd;
    }
}

// ---------------------------------------------------------------------------
// Aggregation. PACK=true: emit bf16 hi/lo packed pairs (R must be 2).
// ---------------------------------------------------------------------------
template <int OUT, int H, int C, bool PACK>
__global__ void k_agg(const float* __restrict__ h, const float* __restrict__ als,
                      const float* __restrict__ ald, const float* __restrict__ emax,
                      const float* __restrict__ dinv, const float* __restrict__ bias,
                      float* __restrict__ outF, uint32_t* __restrict__ outH,
                      uint32_t* __restrict__ outL) {
    constexpr int T = (OUT < 256) ? OUT : 256;
    constexpr int R = OUT / T;
    __shared__ int   ssrc[32];
    __shared__ float salpha[32 * H];
    int n = blockIdx.x, t = threadIdx.x;
    int myhead = (t * R) / C;

    float acc[R];
#pragma unroll
    for (int j = 0; j < R; j++) acc[j] = 0.f;

    int s0 = g_off[n], s1 = g_off[n + 1];
    for (int e0 = s0; e0 < s1; e0 += 32) {
        int cs = min(32, s1 - e0);
        if (t < cs) ssrc[t] = g_srcS[e0 + t];
        __syncthreads();
        if (t < cs * H) {
            int i = t / H, hh = t - i * H;
            float e = als[ssrc[i] * H + hh] + ald[n * H + hh];
            e = fmaxf(e, 0.2f * e);
            salpha[i * H + hh] = __expf(e - emax[n * H + hh]) * dinv[n * H + hh];
        }
        __syncthreads();
        for (int i = 0; i < cs; i++) {
            float a = salpha[i * H + myhead];
            const float* hp = h + (size_t)ssrc[i] * OUT + t * R;
            if constexpr (R == 2) {
                float2 v = *(const float2*)hp;
                acc[0] += a * v.x; acc[1] += a * v.y;
            } else {
                acc[0] += a * hp[0];
            }
        }
        __syncthreads();
    }
    if constexpr (PACK) {
        float v0 = acc[0] + bias[2 * t];
        float v1 = acc[1] + bias[2 * t + 1];
        v0 = (v0 > 0.f) ? v0 : 0.01f * v0;
        v1 = (v1 > 0.f) ? v1 : 0.01f * v1;
        uint32_t ph, pl;
        split_pack(v0, v1, ph, pl);
        outH[(size_t)n * (OUT / 2) + t] = ph;
        outL[(size_t)n * (OUT / 2) + t] = pl;
    } else {
#pragma unroll
        for (int j = 0; j < R; j++) {
            float v = acc[j] + bias[t * R + j];
            outF[(size_t)n * OUT + t * R + j] = (v > 0.f) ? v : 0.01f * v;
        }
    }
}

// ---------------------------------------------------------------------------
// Pooling + head
// ---------------------------------------------------------------------------
__device__ __forceinline__ int lower_bound_b(const int* __restrict__ b, int val) {
    int lo = 0, hi = NN;
    while (lo < hi) {
        int mid = (lo + hi) >> 1;
        if (ld_b(b, mid) < val) lo = mid + 1; else hi = mid;
    }
    return lo;
}

__global__ void k_poolseg(const int* __restrict__ batch, const float* __restrict__ o3,
                          const float* __restrict__ Wout, const float* __restrict__ bout,
                          float* __restrict__ out) {
    int gph = blockIdx.x, t = threadIdx.x;
    int lo = lower_bound_b(batch, gph);
    int hi = lower_bound_b(batch, gph + 1);
    float s = 0.f;
    for (int n = lo; n < hi; n++) s += o3[(size_t)n * 128 + t];
    float cnt = fmaxf((float)(hi - lo), 1.f);
    float v = (s / cnt) * Wout[t];
#pragma unroll
    for (int o = 16; o > 0; o >>= 1) v += __shfl_down_sync(0xFFFFFFFFu, v, o);
    __shared__ float red[4];
    if ((t & 31) == 0) red[t >> 5] = v;
    __syncthreads();
    if (t == 0) out[gph] = red[0] + red[1] + red[2] + red[3] + bout[0];
}

// ---------------------------------------------------------------------------
// Launch
// ---------------------------------------------------------------------------
extern "C" void kernel_launch(void* const* d_in, const int* in_sizes, int n_in,
                              void* d_out, int out_size) {
    int ix = 0, iei = 1, ib = 2, iW1 = 3, ia1s = 4, ia1d = 5, ib1 = 6,
        iW2 = 7, ia2s = 8, ia2d = 9, ib2 = 10, iW3 = 11, ia3s = 12,
        ia3d = 13, ib3 = 14, iWout = 15, ibout = 16;
    {
        int jx = -1, jei = -1, jb = -1, jW1 = -1, jW2 = -1, jW3 = -1, jbout = -1;
        int j1024[3], n1024 = 0;
        int j512[3],  n512 = 0;
        int j128[4],  n128 = 0;
        bool clean = true;
        for (int i = 0; i < n_in; i++) {
            int s = in_sizes[i];
            if      (s == 550000) { if (jx >= 0) clean = false; jx = i; }
            else if (s == 500000) { if (jei >= 0) clean = false; jei = i; }
            else if (s == 50000)  { if (jb >= 0) clean = false; jb = i; }
            else if (s == 11264)  { if (jW1 >= 0) clean = false; jW1 = i; }
            else if (s == 524288) { if (jW2 >= 0) clean = false; jW2 = i; }
            else if (s == 65536)  { if (jW3 >= 0) clean = false; jW3 = i; }
            else if (s == 1024)   { if (n1024 < 3) j1024[n1024] = i; n1024++; }
            else if (s == 512)    { if (n512  < 3) j512[n512]   = i; n512++; }
            else if (s == 128)    { if (n128  < 4) j128[n128]   = i; n128++; }
            else if (s == 1)      { if (jbout >= 0) clean = false; jbout = i; }
            else clean = false;
        }
        if (clean && jx >= 0 && jei >= 0 && jb >= 0 && jW1 >= 0 && jW2 >= 0 &&
            jW3 >= 0 && jbout >= 0 && n1024 == 3 && n512 == 3 && n128 == 4) {
            ix = jx; iei = jei; ib = jb; iW1 = jW1; iW2 = jW2; iW3 = jW3;
            ia1s = j1024[0]; ia1d = j1024[1]; ib1 = j1024[2];
            ia2s = j512[0];  ia2d = j512[1];  ib2 = j512[2];
            ia3s = j128[0];  ia3d = j128[1];  ib3 = j128[2]; iWout = j128[3];
            ibout = jbout;
        }
    }

    const float* x    = (const float*)d_in[ix];
    const int*   ei   = (const int*)d_in[iei];
    const int*   batch= (const int*)d_in[ib];
    const float* W1   = (const float*)d_in[iW1];
    const float* a1s  = (const float*)d_in[ia1s];
    const float* a1d  = (const float*)d_in[ia1d];
    const float* b1   = (const float*)d_in[ib1];
    const float* W2   = (const float*)d_in[iW2];
    const float* a2s  = (const float*)d_in[ia2s];
    const float* a2d  = (const float*)d_in[ia2d];
    const float* b2   = (const float*)d_in[ib2];
    const float* W3   = (const float*)d_in[iW3];
    const float* a3s  = (const float*)d_in[ia3s];
    const float* a3d  = (const float*)d_in[ia3d];
    const float* b3   = (const float*)d_in[ib3];
    const float* Wout = (const float*)d_in[iWout];
    const float* bout = (const float*)d_in[ibout];
    float* out = (float*)d_out;

    float* P = nullptr;      cudaGetSymbolAddress((void**)&P, g_P);
    uint32_t* Qh = nullptr;  cudaGetSymbolAddress((void**)&Qh, g_Qh);
    uint32_t* Ql = nullptr;  cudaGetSymbolAddress((void**)&Ql, g_Ql);
    uint32_t* B2h = nullptr; cudaGetSymbolAddress((void**)&B2h, g_B2h);
    uint32_t* B2l = nullptr; cudaGetSymbolAddress((void**)&B2l, g_B2l);
    uint32_t* B3h = nullptr; cudaGetSymbolAddress((void**)&B3h, g_B3h);
    uint32_t* B3l = nullptr; cudaGetSymbolAddress((void**)&B3l, g_B3l);
    float* als = nullptr;    cudaGetSymbolAddress((void**)&als, g_als);
    float* ald = nullptr;    cudaGetSymbolAddress((void**)&ald, g_ald);
    float* emax = nullptr;   cudaGetSymbolAddress((void**)&emax, g_emax);
    float* dinv = nullptr;   cudaGetSymbolAddress((void**)&dinv, g_dinv);

    static bool attr_set = false;
    if (!attr_set) {
        cudaFuncSetAttribute(k_gemm_bf16, cudaFuncAttributeMaxDynamicSharedMemorySize,
                             GEMM_SMEM);
        attr_set = true;
    }

    // dtype detection + CSR build + weight prep
    k_detect<<<1, 1024>>>(ei, batch);
    k_zero_deg<<<(NN + 255) / 256, 256>>>();
    k_count<<<(ET + 255) / 256, 256>>>(ei);
    k_wprep<<<(512 * 512 + 255) / 256, 256>>>(W2, B2h, B2l, 512, 512);
    k_wprep<<<(256 * 128 + 255) / 256, 256>>>(W3, B3h, B3l, 256, 128);
    k_scan1<<<50, 1024>>>();
    k_scan2<<<1, 32>>>();
    k_scan3<<<50, 1024>>>();
    k_scatter<<<(ET + 255) / 256, 256>>>(ei);

    // ---- Layer 1 (algebraic): o1 -> Qh/Ql packed ----
    k_wsd<<<1, 128>>>(W1, a1s, a1d);
    k_alx<<<(NN + 255) / 256, 256>>>(x);
    k_stats<8><<<(NN * 8 + 255) / 256, 256>>>(als, ald, emax, dinv);
    k_aggx<<<(NN + 127) / 128, 128>>>(x);
    {
        dim3 grid((NN + 63) / 64, 8);
        k_proj<<<grid, 256>>>(W1, b1, Qh, Ql);
    }

    // ---- Layer 2: h2 = o1 @ W2 (bf16x3 TC), agg -> o2 packed ----
    {
        dim3 grid((NN + 127) / 128, 4);
        k_gemm_bf16<<<grid, 256, GEMM_SMEM>>>(Qh, Ql, B2h, B2l, P, NN, 1024, 512);
        k_al<512, 64, 8><<<NN, 256>>>(P, a2s, a2d, als, ald);
        k_stats<8><<<(NN * 8 + 255) / 256, 256>>>(als, ald, emax, dinv);
        k_agg<512, 8, 64, true><<<NN, 256>>>(P, als, ald, emax, dinv, b2,
                                             nullptr, Qh, Ql);
    }

    // ---- Layer 3: h3 = o2 @ W3 (bf16x3 TC), agg -> o3 fp32 ----
    {
        dim3 grid((NN + 127) / 128, 1);
        k_gemm_bf16<<<grid, 256, GEMM_SMEM>>>(Qh, Ql, B3h, B3l, P, NN, 512, 128);
        k_al<128, 32, 4><<<NN, 128>>>(P, a3s, a3d, als, ald);
        k_stats<4><<<(NN * 4 + 255) / 256, 256>>>(als, ald, emax, dinv);
        k_agg<128, 4, 32, false><<<NN, 128>>>(P, als, ald, emax, dinv, b3,
                                              (float*)Qh, nullptr, nullptr);
    }

    // ---- Pool + head ----
    k_poolseg<<<NG, 128>>>(batch, (float*)Qh, Wout, bout, out);
}